// round 1
// baseline (speedup 1.0000x reference)
#include <cuda_runtime.h>
#include <cuda_bf16.h>
#include <math.h>

// ---------------- problem constants ----------------
#define B_    512
#define L_    4
#define M_    8
#define N_    64
#define K_    4
#define CH_   128
#define NP1   65            // N_+1
#define POS   520           // M_*NP1
#define FLAT  33280         // 64*M_*NP1
#define ROWS  2048          // B_*L_
#define JD    256           // 4*N_  (pl1 out)
#define J2D   128           // 2*N_  (pl2 out)
#define NPOS  (ROWS*POS)    // 1064960 total conv positions

#define SPLIT 8
#define KSL   (FLAT/SPLIT)  // 4160
#define BM 128
#define BN 64
#define BK 16

// output layout: W (512*80) | Theta (2048*64*2) | mu (512*2)
#define OFF_THETA 40960
#define OFF_MU    (40960 + 262144)

// ---------------- scratch (no allocations allowed) ----------------
__device__ float g_H[(size_t)ROWS * FLAT];          // 272.6 MB conv output
__device__ float g_Rpart[(size_t)SPLIT * ROWS * JD]; // 16 MB split-K partials
__device__ float g_Theta[2 * ROWS * N_];            // tr | ti
__device__ float g_pl2T[JD * J2D];                  // pl2_w transposed

// ---------------- f32x2 helpers (Blackwell packed FMA) ----------------
__device__ __forceinline__ unsigned long long dup2(float v) {
    unsigned long long r;
    asm("mov.b64 %0, {%1, %1};" : "=l"(r) : "f"(v));
    return r;
}
__device__ __forceinline__ void fma2(unsigned long long& d,
                                     unsigned long long a,
                                     unsigned long long b) {
    asm("fma.rn.f32x2 %0, %1, %2, %0;" : "+l"(d) : "l"(a), "l"(b));
}
__device__ __forceinline__ float2 unpack2(unsigned long long v) {
    float2 r;
    asm("mov.b64 {%0, %1}, %2;" : "=f"(r.x), "=f"(r.y) : "l"(v));
    return r;
}

// ---------------- K0: transpose pl2_w (128x256 -> 256x128) ----------------
__global__ void k0_transpose(const float* __restrict__ pl2_w) {
    int idx = blockIdx.x * 256 + threadIdx.x;   // 32768 total
    int i = idx >> 7;        // 0..255
    int j = idx & 127;       // 0..127
    g_pl2T[idx] = pl2_w[j * JD + i];
}

// ---------------- K1: fused conv1+conv2 -> g_H ----------------
__global__ void __launch_bounds__(256) k1_conv(
    const float* __restrict__ x,
    const float* __restrict__ w1, const float* __restrict__ b1,
    const float* __restrict__ w2, const float* __restrict__ b2)
{
    __shared__ float w1s[64 * 8], b1s[64], b2s[64];
    __shared__ float w2s[64 * 64];
    int tid = threadIdx.x;
    for (int i = tid; i < 512; i += 256) w1s[i] = w1[i];
    if (tid < 64) { b1s[tid] = b1[tid]; b2s[tid] = b2[tid]; }
    for (int i = tid; i < 4096; i += 256) w2s[i] = w2[i];
    __syncthreads();

    int p = blockIdx.x * 256 + tid;       // NPOS = 4160*256 exactly
    int bl = p / POS;
    int q  = p - bl * POS;                // m*65+n
    const float* xp = x + (size_t)bl * (8 * POS) + q;

    float xv[8];
#pragma unroll
    for (int c = 0; c < 8; c++) xv[c] = xp[c * POS];

    float h1[64];
#pragma unroll
    for (int o = 0; o < 64; o++) {
        float a = b1s[o];
#pragma unroll
        for (int c = 0; c < 8; c++) a += xv[c] * w1s[o * 8 + c];
        h1[o] = fmaxf(a, 0.f);
    }

    float* Hp = g_H + (size_t)bl * FLAT + q;
    const float4* w2s4 = (const float4*)w2s;
#pragma unroll 4
    for (int o2 = 0; o2 < 64; o2++) {
        float a = b2s[o2];
#pragma unroll
        for (int o4 = 0; o4 < 16; o4++) {
            float4 w = w2s4[o2 * 16 + o4];
            a += h1[4 * o4 + 0] * w.x;
            a += h1[4 * o4 + 1] * w.y;
            a += h1[4 * o4 + 2] * w.z;
            a += h1[4 * o4 + 3] * w.w;
        }
        Hp[o2 * POS] = fmaxf(a, 0.f);
    }
}

// ---------------- K2: split-K SGEMM (f32x2 packed FMA) ----------------
// g_Rpart[sp][row][j] = sum_{k in slice} g_H[row][k] * pl1_w[j][k]
__global__ void __launch_bounds__(256) k2_gemm(const float* __restrict__ Bw)
{
    __shared__ __align__(16) float As[BK][BM];
    __shared__ __align__(16) float Bs[BK][BN];

    int tid  = threadIdx.x;
    int row0 = blockIdx.x * BM;     // 16 blocks
    int col0 = blockIdx.y * BN;     // 4 blocks
    int sp   = blockIdx.z;          // 8 splits
    int k0   = sp * KSL;

    int ty = tid >> 4;      // 0..15  -> rows ty*8..+8
    int tx = tid & 15;      // 0..15  -> cols tx*4..+4

    int lr  = tid >> 2;        // 0..63
    int lkq = (tid & 3) * 4;   // 0,4,8,12

    const float* Aptr = g_H + (size_t)row0 * FLAT + k0;
    const float* Bptr = Bw  + (size_t)col0 * FLAT + k0;

    unsigned long long acc[4][4];
#pragma unroll
    for (int i = 0; i < 4; i++)
#pragma unroll
        for (int j = 0; j < 4; j++) acc[i][j] = 0ULL;

    for (int kk = 0; kk < KSL; kk += BK) {
        // load A tile: 128 rows x 16 k
#pragma unroll
        for (int h = 0; h < 2; h++) {
            int r = lr + h * 64;
            float4 v = *(const float4*)(Aptr + (size_t)r * FLAT + kk + lkq);
            As[lkq + 0][r] = v.x;
            As[lkq + 1][r] = v.y;
            As[lkq + 2][r] = v.z;
            As[lkq + 3][r] = v.w;
        }
        // load B tile: 64 rows x 16 k
        {
            float4 v = *(const float4*)(Bptr + (size_t)lr * FLAT + kk + lkq);
            Bs[lkq + 0][lr] = v.x;
            Bs[lkq + 1][lr] = v.y;
            Bs[lkq + 2][lr] = v.z;
            Bs[lkq + 3][lr] = v.w;
        }
        __syncthreads();

#pragma unroll
        for (int k = 0; k < BK; k++) {
            ulonglong2 a01 = *(const ulonglong2*)&As[k][ty * 8];
            ulonglong2 a23 = *(const ulonglong2*)&As[k][ty * 8 + 4];
            float4 bv = *(const float4*)&Bs[k][tx * 4];
            unsigned long long bd0 = dup2(bv.x);
            unsigned long long bd1 = dup2(bv.y);
            unsigned long long bd2 = dup2(bv.z);
            unsigned long long bd3 = dup2(bv.w);
            fma2(acc[0][0], a01.x, bd0); fma2(acc[0][1], a01.x, bd1);
            fma2(acc[0][2], a01.x, bd2); fma2(acc[0][3], a01.x, bd3);
            fma2(acc[1][0], a01.y, bd0); fma2(acc[1][1], a01.y, bd1);
            fma2(acc[1][2], a01.y, bd2); fma2(acc[1][3], a01.y, bd3);
            fma2(acc[2][0], a23.x, bd0); fma2(acc[2][1], a23.x, bd1);
            fma2(acc[2][2], a23.x, bd2); fma2(acc[2][3], a23.x, bd3);
            fma2(acc[3][0], a23.y, bd0); fma2(acc[3][1], a23.y, bd1);
            fma2(acc[3][2], a23.y, bd2); fma2(acc[3][3], a23.y, bd3);
        }
        __syncthreads();
    }

    float* outp = g_Rpart + ((size_t)sp * ROWS + row0 + ty * 8) * JD + col0 + tx * 4;
#pragma unroll
    for (int ip = 0; ip < 4; ip++) {
        float2 c0 = unpack2(acc[ip][0]);
        float2 c1 = unpack2(acc[ip][1]);
        float2 c2 = unpack2(acc[ip][2]);
        float2 c3 = unpack2(acc[ip][3]);
        float4 lo = make_float4(c0.x, c1.x, c2.x, c3.x);
        float4 hi = make_float4(c0.y, c1.y, c2.y, c3.y);
        *(float4*)(outp + (size_t)(2 * ip) * JD)     = lo;
        *(float4*)(outp + (size_t)(2 * ip + 1) * JD) = hi;
    }
}

// ---------------- K3: split-K reduce + bias/relu + pl2 + Theta ----------------
__global__ void __launch_bounds__(256) k3_epi(
    const float* __restrict__ pl1_b,
    const float* __restrict__ pl2_b,
    float* __restrict__ outTheta)
{
    __shared__ float Hs[8][JD];
    __shared__ float Rls[8][J2D];
    int r0  = blockIdx.x * 8;   // 256 blocks
    int tid = threadIdx.x;

#pragma unroll
    for (int rr = 0; rr < 8; rr++) {
        size_t base = (size_t)(r0 + rr) * JD + tid;
        float s = 0.f;
#pragma unroll
        for (int sp = 0; sp < SPLIT; sp++)
            s += g_Rpart[(size_t)sp * ROWS * JD + base];
        Hs[rr][tid] = fmaxf(s + pl1_b[tid], 0.f);
    }
    __syncthreads();

    int j = tid & 127;
    int half = tid >> 7;
    float acc[4];
#pragma unroll
    for (int rr = 0; rr < 4; rr++) acc[rr] = pl2_b[j];
    for (int i = 0; i < JD; i++) {
        float w = g_pl2T[i * J2D + j];
#pragma unroll
        for (int rr = 0; rr < 4; rr++) acc[rr] += Hs[half * 4 + rr][i] * w;
    }
#pragma unroll
    for (int rr = 0; rr < 4; rr++) Rls[half * 4 + rr][j] = acc[rr];
    __syncthreads();

    for (int t = tid; t < 8 * N_; t += 256) {
        int rr = t >> 6, n = t & 63;
        float pr = Rls[rr][n];
        float pi = Rls[rr][n + N_];
        float nm = fmaxf(sqrtf(pr * pr + pi * pi), 1e-12f);
        float tr = pr / nm, ti = pi / nm;
        int r = r0 + rr;
        outTheta[((size_t)r * N_ + n) * 2 + 0] = tr;
        outTheta[((size_t)r * N_ + n) * 2 + 1] = ti;
        g_Theta[r * N_ + n] = tr;
        g_Theta[ROWS * N_ + r * N_ + n] = ti;
    }
}

// ---------------- K4: per-batch H einsums + MLP heads ----------------
__global__ void __launch_bounds__(256) k4_head(
    const float* __restrict__ H_re, const float* __restrict__ H_im,
    const float* __restrict__ ch_re, const float* __restrict__ ch_im,
    const float* __restrict__ b1_w, const float* __restrict__ b1_b,
    const float* __restrict__ b2_w, const float* __restrict__ b2_b,
    const float* __restrict__ b3_w, const float* __restrict__ b3_b,
    const float* __restrict__ p1_w, const float* __restrict__ p1_b,
    const float* __restrict__ p2_w, const float* __restrict__ p2_b,
    float* __restrict__ outW, float* __restrict__ outMu)
{
    int b = blockIdx.x;
    int tid = threadIdx.x;
    __shared__ float trs[256], tis[256];                 // [l*64+n]
    __shared__ float cHs[64], W1s[128], P1s[128], W2s[128], W3s[80];
    __shared__ float MUs[2], SCs[1];

    trs[tid] = g_Theta[b * 256 + tid];
    tis[tid] = g_Theta[ROWS * N_ + b * 256 + tid];
    __syncthreads();

    // top/bot einsums: out = k*8+m, 8 lanes per output
    int out = tid >> 3;       // 0..31
    int g   = tid & 7;
    int kk  = out >> 3;       // 0..3
    int mm  = out & 7;        // 0..7
    const float* hre = H_re + (size_t)b * 8192;
    const float* him = H_im + (size_t)b * 8192;
    float s_rr = 0.f, s_ii = 0.f, s_ri = 0.f, s_ir = 0.f;
    for (int t = g; t < 256; t += 8) {
        int n = t >> 2, l = t & 3;
        float tr = trs[l * 64 + n];
        float ti = tis[l * 64 + n];
        int idx = mm * 1024 + n * 16 + l * 4 + kk;
        float hr = hre[idx];
        float hi = him[idx];
        s_rr += hr * tr; s_ii += hi * ti;
        s_ri += hr * ti; s_ir += hi * tr;
    }
#pragma unroll
    for (int off = 4; off; off >>= 1) {
        s_rr += __shfl_down_sync(0xffffffffu, s_rr, off, 8);
        s_ii += __shfl_down_sync(0xffffffffu, s_ii, off, 8);
        s_ri += __shfl_down_sync(0xffffffffu, s_ri, off, 8);
        s_ir += __shfl_down_sync(0xffffffffu, s_ir, off, 8);
    }
    if (g == 0) {
        cHs[kk * 16 + mm]     = s_rr + s_ii + ch_re[(b * 4 + kk) * 8 + mm];
        cHs[kk * 16 + 8 + mm] = s_ri - s_ir + ch_im[(b * 4 + kk) * 8 + mm];
    }
    __syncthreads();

    if (tid < 128) {
        float a = b1_b[tid];
        for (int c = 0; c < 64; c++) a += b1_w[tid * 64 + c] * cHs[c];
        W1s[tid] = fmaxf(a, 0.f);
    } else {
        int jj = tid - 128;
        float a = p1_b[jj];
        for (int c = 0; c < 64; c++) a += p1_w[jj * 64 + c] * cHs[c];
        P1s[jj] = fmaxf(a, 0.f);
    }
    __syncthreads();

    if (tid < 128) {
        float a = b2_b[tid];
        for (int c = 0; c < 128; c++) a += b2_w[tid * 128 + c] * W1s[c];
        W2s[tid] = fmaxf(a, 0.f);
    } else if (tid < 130) {
        int m2 = tid - 128;
        float a = p2_b[m2];
        for (int c = 0; c < 128; c++) a += p2_w[m2 * 128 + c] * P1s[c];
        MUs[m2] = a;
    }
    __syncthreads();

    if (tid < 80) {
        float a = b3_b[tid];
        for (int c = 0; c < 128; c++) a += b3_w[tid * 128 + c] * W2s[c];
        W3s[tid] = a;
    }
    __syncthreads();

    if (tid == 0) {
        float ss = 0.f;
        for (int j = 0; j < 80; j++) ss += W3s[j] * W3s[j];
        float wn = fmaxf(sqrtf(ss), 1e-12f);
        float mx = fmaxf(MUs[0], MUs[1]);
        float e0 = expf(MUs[0] - mx), e1 = expf(MUs[1] - mx);
        float mu0 = e0 / (e0 + e1);
        MUs[0] = mu0;
        MUs[1] = e1 / (e0 + e1);
        SCs[0] = sqrtf(10.0f) * sqrtf(mu0) / wn;
    }
    __syncthreads();

    if (tid < 80) outW[b * 80 + tid] = W3s[tid] * SCs[0];
    if (tid < 2)  outMu[b * 2 + tid] = MUs[tid];
}

// ---------------- launch ----------------
extern "C" void kernel_launch(void* const* d_in, const int* in_sizes, int n_in,
                              void* d_out, int out_size)
{
    const float* x       = (const float*)d_in[0];
    const float* H_re    = (const float*)d_in[1];
    const float* H_im    = (const float*)d_in[2];
    const float* ch_re   = (const float*)d_in[3];
    const float* ch_im   = (const float*)d_in[4];
    const float* conv1_w = (const float*)d_in[5];
    const float* conv1_b = (const float*)d_in[6];
    const float* conv2_w = (const float*)d_in[7];
    const float* conv2_b = (const float*)d_in[8];
    const float* pl1_w   = (const float*)d_in[9];
    const float* pl1_b   = (const float*)d_in[10];
    const float* pl2_w   = (const float*)d_in[11];
    const float* pl2_b   = (const float*)d_in[12];
    const float* b1_w    = (const float*)d_in[13];
    const float* b1_b    = (const float*)d_in[14];
    const float* b2_w    = (const float*)d_in[15];
    const float* b2_b    = (const float*)d_in[16];
    const float* b3_w    = (const float*)d_in[17];
    const float* b3_b    = (const float*)d_in[18];
    const float* p1_w    = (const float*)d_in[19];
    const float* p1_b    = (const float*)d_in[20];
    const float* p2_w    = (const float*)d_in[21];
    const float* p2_b    = (const float*)d_in[22];

    float* out      = (float*)d_out;
    float* outW     = out;
    float* outTheta = out + OFF_THETA;
    float* outMu    = out + OFF_MU;

    k0_transpose<<<128, 256>>>(pl2_w);
    k1_conv<<<NPOS / 256, 256>>>(x, conv1_w, conv1_b, conv2_w, conv2_b);
    dim3 g2(ROWS / BM, JD / BN, SPLIT);
    k2_gemm<<<g2, 256>>>(pl1_w);
    k3_epi<<<ROWS / 8, 256>>>(pl1_b, pl2_b, outTheta);
    k4_head<<<B_, 256>>>(H_re, H_im, ch_re, ch_im,
                         b1_w, b1_b, b2_w, b2_b, b3_w, b3_b,
                         p1_w, p1_b, p2_w, p2_b, outW, outMu);
}

// round 3
// speedup vs baseline: 2.0119x; 2.0119x over previous
#include <cuda_runtime.h>
#include <cuda_bf16.h>
#include <math.h>
#include <stdint.h>

// ---------------- problem constants ----------------
#define B_    512
#define L_    4
#define M_    8
#define N_    64
#define K_    4
#define NP1   65            // N_+1
#define POS   520           // M_*NP1
#define FLAT  33280         // 64*M_*NP1
#define ROWS  2048          // B_*L_
#define JD    256           // 4*N_  (pl1 out)
#define J2D   128           // 2*N_  (pl2 out)
#define NPOS  (ROWS*POS)    // 1064960 conv positions

#define SPLIT 8
#define KSL   (FLAT/SPLIT)  // 4160
#define GKC   32            // K per smem chunk
#define NCHUNK (KSL/GKC)    // 130

// output layout: W (512*80) | Theta (2048*64*2) | mu (512*2)
#define OFF_THETA 40960
#define OFF_MU    (40960 + 262144)

// ---------------- scratch (no allocations allowed) ----------------
__device__ float g_H[(size_t)ROWS * FLAT];            // conv output (tf32-rounded)
__device__ float g_Bw[(size_t)JD * FLAT];             // pl1_w tf32-rounded
__device__ float g_Rpart[(size_t)SPLIT * ROWS * JD];  // split-K partials
__device__ float g_Theta[2 * ROWS * N_];              // tr | ti
__device__ float g_pl2T[JD * J2D];                    // pl2_w transposed

// ---------------- helpers: packed f32x2 ----------------
__device__ __forceinline__ unsigned long long pack2(float a, float b) {
    unsigned long long r;
    asm("mov.b64 %0, {%1, %2};" : "=l"(r) : "f"(a), "f"(b));
    return r;
}
__device__ __forceinline__ void fma2(unsigned long long& d,
                                     unsigned long long a,
                                     unsigned long long b) {
    asm("fma.rn.f32x2 %0, %1, %2, %0;" : "+l"(d) : "l"(a), "l"(b));
}
__device__ __forceinline__ float2 unpack2(unsigned long long v) {
    float2 r;
    asm("mov.b64 {%0, %1}, %2;" : "=f"(r.x), "=f"(r.y) : "l"(v));
    return r;
}
__device__ __forceinline__ uint32_t to_tf32(float v) {
    uint32_t u;
    asm("cvt.rna.tf32.f32 %0, %1;" : "=r"(u) : "f"(v));
    return u;
}

// ---------------- helpers: cp.async ----------------
__device__ __forceinline__ uint32_t smem_u32(const void* p) {
    uint32_t a;
    asm("{ .reg .u64 t; cvta.to.shared.u64 t, %1; cvt.u32.u64 %0, t; }" : "=r"(a) : "l"(p));
    return a;
}
#define CPASYNC16(sa, gp)  asm volatile("cp.async.cg.shared.global [%0], [%1], 16;" :: "r"(sa), "l"(gp) : "memory")
#define CP_COMMIT()        asm volatile("cp.async.commit_group;" ::: "memory")
#define CP_WAIT0()         asm volatile("cp.async.wait_group 0;" ::: "memory")
#define CP_WAIT1()         asm volatile("cp.async.wait_group 1;" ::: "memory")

// mma.sync tf32 (family-portable HMMA path; tcgen05 is rejected by this toolchain)
__device__ __forceinline__ void mma_tf32(float* d, const uint32_t* a, const uint32_t* b) {
    asm volatile(
        "mma.sync.aligned.m16n8k8.row.col.f32.tf32.tf32.f32 "
        "{%0,%1,%2,%3}, {%4,%5,%6,%7}, {%8,%9}, {%0,%1,%2,%3};"
        : "+f"(d[0]), "+f"(d[1]), "+f"(d[2]), "+f"(d[3])
        : "r"(a[0]), "r"(a[1]), "r"(a[2]), "r"(a[3]), "r"(b[0]), "r"(b[1]));
}

// ---------------- K0: transpose pl2_w (128x256 -> 256x128) ----------------
__global__ void k0_transpose(const float* __restrict__ pl2_w) {
    int idx = blockIdx.x * 256 + threadIdx.x;
    int i = idx >> 7;
    int j = idx & 127;
    g_pl2T[idx] = pl2_w[j * JD + i];
}

// ---------------- K0b: round pl1_w to tf32 -> g_Bw ----------------
__global__ void k0b_round(const float* __restrict__ w) {
    size_t i = ((size_t)blockIdx.x * 256 + threadIdx.x) * 4;
    float4 v = *(const float4*)(w + i);
    v.x = __uint_as_float(to_tf32(v.x));
    v.y = __uint_as_float(to_tf32(v.y));
    v.z = __uint_as_float(to_tf32(v.z));
    v.w = __uint_as_float(to_tf32(v.w));
    *(float4*)(g_Bw + i) = v;
}

// ---------------- K1: fused conv1+conv2 -> g_H (tf32-rounded), f32x2 path ----
__global__ void __launch_bounds__(256) k1_conv(
    const float* __restrict__ x,
    const float* __restrict__ w1, const float* __restrict__ b1,
    const float* __restrict__ w2, const float* __restrict__ b2)
{
    __shared__ __align__(16) float w1s[64 * 8];
    __shared__ float b1s[64], b2s[64];
    __shared__ __align__(16) float w2s[64 * 64];
    int tid = threadIdx.x;
    for (int i = tid; i < 512; i += 256) w1s[i] = w1[i];
    if (tid < 64) { b1s[tid] = b1[tid]; b2s[tid] = b2[tid]; }
    for (int i = tid; i < 4096; i += 256) w2s[i] = w2[i];
    __syncthreads();

    int p = blockIdx.x * 256 + tid;
    int bl = p / POS;
    int q  = p - bl * POS;
    const float* xp = x + (size_t)bl * (8 * POS) + q;

    unsigned long long xv2[4];
#pragma unroll
    for (int c = 0; c < 4; c++)
        xv2[c] = pack2(xp[(2 * c) * POS], xp[(2 * c + 1) * POS]);

    const unsigned long long* w1p = (const unsigned long long*)w1s;
    unsigned long long h2[32];
#pragma unroll
    for (int i = 0; i < 32; i++) {
        unsigned long long a0 = 0ULL, a1 = 0ULL;
#pragma unroll
        for (int c = 0; c < 4; c++) {
            fma2(a0, xv2[c], w1p[(2 * i) * 4 + c]);
            fma2(a1, xv2[c], w1p[(2 * i + 1) * 4 + c]);
        }
        float2 f0 = unpack2(a0), f1 = unpack2(a1);
        float v0 = fmaxf(f0.x + f0.y + b1s[2 * i], 0.f);
        float v1 = fmaxf(f1.x + f1.y + b1s[2 * i + 1], 0.f);
        h2[i] = pack2(v0, v1);
    }

    float* Hp = g_H + (size_t)bl * FLAT + q;
#pragma unroll 4
    for (int o2 = 0; o2 < 64; o2++) {
        unsigned long long acc = 0ULL;
        const ulonglong2* ww = (const ulonglong2*)(w2s + o2 * 64);
#pragma unroll
        for (int i = 0; i < 16; i++) {
            ulonglong2 w = ww[i];
            fma2(acc, h2[2 * i], w.x);
            fma2(acc, h2[2 * i + 1], w.y);
        }
        float2 f = unpack2(acc);
        float v = fmaxf(f.x + f.y + b2s[o2], 0.f);
        Hp[o2 * POS] = __uint_as_float(to_tf32(v));
    }
}

// ---------------- K2: mma.sync tf32 split-K GEMM ----------------
// CTA 128x128, Kc=32 double-buffered; 4 warps (2x2), warp tile 64x64.
// grid (16 M, 2 N, 8 split)
#define KPAD   36                        // 32 + 4 pad (floats)
#define TILE_F (128 * KPAD)              // floats per tile buffer
#define TILE_B (TILE_F * 4)              // 18432 bytes
#define SM_DYN (4 * TILE_B)              // A0 A1 B0 B1 = 73728

__device__ __forceinline__ void k2_load_tile(
    int tid, uint32_t sa, uint32_t sb,
    const float* __restrict__ Ab, const float* __restrict__ Bb)
{
    // 128 rows x 32 floats = 1024 x 16B each for A and B; 128 threads
#pragma unroll
    for (int j = 0; j < 8; j++) {
        int u = tid + j * 128;
        int r = u >> 3, qd = u & 7;
        uint32_t so = (uint32_t)(r * (KPAD * 4) + qd * 16);
        CPASYNC16(sa + so, Ab + (size_t)r * FLAT + qd * 4);
        CPASYNC16(sb + so, Bb + (size_t)r * FLAT + qd * 4);
    }
}

__global__ void __launch_bounds__(128) k2_mma()
{
    extern __shared__ float smem[];
    uint32_t sbase = smem_u32(smem);
    float* Abuf[2] = { smem,              smem + TILE_F };
    float* Bbuf[2] = { smem + 2 * TILE_F, smem + 3 * TILE_F };
    uint32_t aAddr[2] = { sbase,              sbase + TILE_B };
    uint32_t bAddr[2] = { sbase + 2 * TILE_B, sbase + 3 * TILE_B };

    int tid = threadIdx.x;
    int w   = tid >> 5, lane = tid & 31;
    int g   = lane >> 2, tg = lane & 3;
    int wm  = (w >> 1) * 64;   // warp M offset
    int wn  = (w & 1) * 64;    // warp N offset

    int row0 = blockIdx.x * 128;
    int col0 = blockIdx.y * 128;
    int sp   = blockIdx.z;
    int k0   = sp * KSL;

    const float* Ab = g_H  + (size_t)row0 * FLAT + k0;
    const float* Bb = g_Bw + (size_t)col0 * FLAT + k0;

    float acc[4][8][4];
#pragma unroll
    for (int i = 0; i < 4; i++)
#pragma unroll
        for (int j = 0; j < 8; j++)
#pragma unroll
            for (int c = 0; c < 4; c++) acc[i][j][c] = 0.f;

    k2_load_tile(tid, aAddr[0], bAddr[0], Ab, Bb);
    CP_COMMIT();

    for (int it = 0; it < NCHUNK; it++) {
        int cur = it & 1;
        if (it + 1 < NCHUNK) {
            k2_load_tile(tid, aAddr[cur ^ 1], bAddr[cur ^ 1],
                         Ab + (size_t)(it + 1) * GKC, Bb + (size_t)(it + 1) * GKC);
            CP_COMMIT();
            CP_WAIT1();
        } else {
            CP_WAIT0();
        }
        __syncthreads();

        const uint32_t* As = (const uint32_t*)Abuf[cur];
        const uint32_t* Bs = (const uint32_t*)Bbuf[cur];
#pragma unroll
        for (int kk = 0; kk < GKC; kk += 8) {
            uint32_t af[4][4], bf[8][2];
#pragma unroll
            for (int i = 0; i < 4; i++) {
                int rbase = (wm + i * 16 + g) * KPAD + kk;
                af[i][0] = As[rbase + tg];
                af[i][1] = As[rbase + 8 * KPAD + tg];
                af[i][2] = As[rbase + tg + 4];
                af[i][3] = As[rbase + 8 * KPAD + tg + 4];
            }
#pragma unroll
            for (int j = 0; j < 8; j++) {
                int rbase = (wn + j * 8 + g) * KPAD + kk;
                bf[j][0] = Bs[rbase + tg];
                bf[j][1] = Bs[rbase + tg + 4];
            }
#pragma unroll
            for (int i = 0; i < 4; i++)
#pragma unroll
                for (int j = 0; j < 8; j++)
                    mma_tf32(acc[i][j], af[i], bf[j]);
        }
        __syncthreads();
    }

    // epilogue: write partials
    float* Rp = g_Rpart + (size_t)sp * ROWS * JD;
#pragma unroll
    for (int i = 0; i < 4; i++) {
        int r = row0 + wm + i * 16 + g;
#pragma unroll
        for (int j = 0; j < 8; j++) {
            int c = col0 + wn + j * 8 + tg * 2;
            *(float2*)(Rp + (size_t)r * JD + c) =
                make_float2(acc[i][j][0], acc[i][j][1]);
            *(float2*)(Rp + (size_t)(r + 8) * JD + c) =
                make_float2(acc[i][j][2], acc[i][j][3]);
        }
    }
}

// ---------------- K3: split-K reduce + bias/relu + pl2 + Theta ----------------
__global__ void __launch_bounds__(256) k3_epi(
    const float* __restrict__ pl1_b,
    const float* __restrict__ pl2_b,
    float* __restrict__ outTheta)
{
    __shared__ float Hs[8][JD];
    __shared__ float Rls[8][J2D];
    int r0  = blockIdx.x * 8;
    int tid = threadIdx.x;

#pragma unroll
    for (int rr = 0; rr < 8; rr++) {
        size_t base = (size_t)(r0 + rr) * JD + tid;
        float s = 0.f;
#pragma unroll
        for (int sp = 0; sp < SPLIT; sp++)
            s += g_Rpart[(size_t)sp * ROWS * JD + base];
        Hs[rr][tid] = fmaxf(s + pl1_b[tid], 0.f);
    }
    __syncthreads();

    int j = tid & 127;
    int half = tid >> 7;
    float acc[4];
#pragma unroll
    for (int rr = 0; rr < 4; rr++) acc[rr] = pl2_b[j];
    for (int i = 0; i < JD; i++) {
        float w = g_pl2T[i * J2D + j];
#pragma unroll
        for (int rr = 0; rr < 4; rr++) acc[rr] += Hs[half * 4 + rr][i] * w;
    }
#pragma unroll
    for (int rr = 0; rr < 4; rr++) Rls[half * 4 + rr][j] = acc[rr];
    __syncthreads();

    for (int t = tid; t < 8 * N_; t += 256) {
        int rr = t >> 6, n = t & 63;
        float pr = Rls[rr][n];
        float pi = Rls[rr][n + N_];
        float nm = fmaxf(sqrtf(pr * pr + pi * pi), 1e-12f);
        float tr = pr / nm, ti = pi / nm;
        int r = r0 + rr;
        outTheta[((size_t)r * N_ + n) * 2 + 0] = tr;
        outTheta[((size_t)r * N_ + n) * 2 + 1] = ti;
        g_Theta[r * N_ + n] = tr;
        g_Theta[ROWS * N_ + r * N_ + n] = ti;
    }
}

// ---------------- K4: per-batch H einsums + MLP heads ----------------
__global__ void __launch_bounds__(256) k4_head(
    const float* __restrict__ H_re, const float* __restrict__ H_im,
    const float* __restrict__ ch_re, const float* __restrict__ ch_im,
    const float* __restrict__ b1_w, const float* __restrict__ b1_b,
    const float* __restrict__ b2_w, const float* __restrict__ b2_b,
    const float* __restrict__ b3_w, const float* __restrict__ b3_b,
    const float* __restrict__ p1_w, const float* __restrict__ p1_b,
    const float* __restrict__ p2_w, const float* __restrict__ p2_b,
    float* __restrict__ outW, float* __restrict__ outMu)
{
    int b = blockIdx.x;
    int tid = threadIdx.x;
    __shared__ float trs[256], tis[256];
    __shared__ float cHs[64], W1s[128], P1s[128], W2s[128], W3s[80];
    __shared__ float MUs[2], SCs[1];

    trs[tid] = g_Theta[b * 256 + tid];
    tis[tid] = g_Theta[ROWS * N_ + b * 256 + tid];
    __syncthreads();

    int out = tid >> 3;
    int g   = tid & 7;
    int kk  = out >> 3;
    int mm  = out & 7;
    const float* hre = H_re + (size_t)b * 8192;
    const float* him = H_im + (size_t)b * 8192;
    float s_rr = 0.f, s_ii = 0.f, s_ri = 0.f, s_ir = 0.f;
    for (int t = g; t < 256; t += 8) {
        int n = t >> 2, l = t & 3;
        float tr = trs[l * 64 + n];
        float ti = tis[l * 64 + n];
        int idx = mm * 1024 + n * 16 + l * 4 + kk;
        float hr = hre[idx];
        float hi = him[idx];
        s_rr += hr * tr; s_ii += hi * ti;
        s_ri += hr * ti; s_ir += hi * tr;
    }
#pragma unroll
    for (int off = 4; off; off >>= 1) {
        s_rr += __shfl_down_sync(0xffffffffu, s_rr, off, 8);
        s_ii += __shfl_down_sync(0xffffffffu, s_ii, off, 8);
        s_ri += __shfl_down_sync(0xffffffffu, s_ri, off, 8);
        s_ir += __shfl_down_sync(0xffffffffu, s_ir, off, 8);
    }
    if (g == 0) {
        cHs[kk * 16 + mm]     = s_rr + s_ii + ch_re[(b * 4 + kk) * 8 + mm];
        cHs[kk * 16 + 8 + mm] = s_ri - s_ir + ch_im[(b * 4 + kk) * 8 + mm];
    }
    __syncthreads();

    if (tid < 128) {
        float a = b1_b[tid];
        for (int c = 0; c < 64; c++) a += b1_w[tid * 64 + c] * cHs[c];
        W1s[tid] = fmaxf(a, 0.f);
    } else {
        int jj = tid - 128;
        float a = p1_b[jj];
        for (int c = 0; c < 64; c++) a += p1_w[jj * 64 + c] * cHs[c];
        P1s[jj] = fmaxf(a, 0.f);
    }
    __syncthreads();

    if (tid < 128) {
        float a = b2_b[tid];
        for (int c = 0; c < 128; c++) a += b2_w[tid * 128 + c] * W1s[c];
        W2s[tid] = fmaxf(a, 0.f);
    } else if (tid < 130) {
        int m2 = tid - 128;
        float a = p2_b[m2];
        for (int c = 0; c < 128; c++) a += p2_w[m2 * 128 + c] * P1s[c];
        MUs[m2] = a;
    }
    __syncthreads();

    if (tid < 80) {
        float a = b3_b[tid];
        for (int c = 0; c < 128; c++) a += b3_w[tid * 128 + c] * W2s[c];
        W3s[tid] = a;
    }
    __syncthreads();

    if (tid == 0) {
        float ss = 0.f;
        for (int j = 0; j < 80; j++) ss += W3s[j] * W3s[j];
        float wn = fmaxf(sqrtf(ss), 1e-12f);
        float mx = fmaxf(MUs[0], MUs[1]);
        float e0 = expf(MUs[0] - mx), e1 = expf(MUs[1] - mx);
        float mu0 = e0 / (e0 + e1);
        MUs[0] = mu0;
        MUs[1] = e1 / (e0 + e1);
        SCs[0] = sqrtf(10.0f) * sqrtf(mu0) / wn;
    }
    __syncthreads();

    if (tid < 80) outW[b * 80 + tid] = W3s[tid] * SCs[0];
    if (tid < 2)  outMu[b * 2 + tid] = MUs[tid];
}

// ---------------- launch ----------------
extern "C" void kernel_launch(void* const* d_in, const int* in_sizes, int n_in,
                              void* d_out, int out_size)
{
    const float* x       = (const float*)d_in[0];
    const float* H_re    = (const float*)d_in[1];
    const float* H_im    = (const float*)d_in[2];
    const float* ch_re   = (const float*)d_in[3];
    const float* ch_im   = (const float*)d_in[4];
    const float* conv1_w = (const float*)d_in[5];
    const float* conv1_b = (const float*)d_in[6];
    const float* conv2_w = (const float*)d_in[7];
    const float* conv2_b = (const float*)d_in[8];
    const float* pl1_w   = (const float*)d_in[9];
    const float* pl1_b   = (const float*)d_in[10];
    const float* pl2_w   = (const float*)d_in[11];
    const float* pl2_b   = (const float*)d_in[12];
    const float* b1_w    = (const float*)d_in[13];
    const float* b1_b    = (const float*)d_in[14];
    const float* b2_w    = (const float*)d_in[15];
    const float* b2_b    = (const float*)d_in[16];
    const float* b3_w    = (const float*)d_in[17];
    const float* b3_b    = (const float*)d_in[18];
    const float* p1_w    = (const float*)d_in[19];
    const float* p1_b    = (const float*)d_in[20];
    const float* p2_w    = (const float*)d_in[21];
    const float* p2_b    = (const float*)d_in[22];

    float* out      = (float*)d_out;
    float* outW     = out;
    float* outTheta = out + OFF_THETA;
    float* outMu    = out + OFF_MU;

    cudaFuncSetAttribute(k2_mma, cudaFuncAttributeMaxDynamicSharedMemorySize, SM_DYN);

    k0_transpose<<<128, 256>>>(pl2_w);
    k0b_round<<<(JD * FLAT) / (256 * 4), 256>>>(pl1_w);
    k1_conv<<<NPOS / 256, 256>>>(x, conv1_w, conv1_b, conv2_w, conv2_b);
    dim3 g2(ROWS / 128, JD / 128, SPLIT);
    k2_mma<<<g2, 128, SM_DYN>>>();
    k3_epi<<<ROWS / 8, 256>>>(pl1_b, pl2_b, outTheta);
    k4_head<<<B_, 256>>>(H_re, H_im, ch_re, ch_im,
                         b1_w, b1_b, b2_w, b2_b, b3_w, b3_b,
                         p1_w, p1_b, p2_w, p2_b, outW, outMu);
}

// round 4
// speedup vs baseline: 2.3125x; 1.1494x over previous
#include <cuda_runtime.h>
#include <cuda_bf16.h>
#include <math.h>
#include <stdint.h>

// ---------------- problem constants ----------------
#define B_    512
#define L_    4
#define M_    8
#define N_    64
#define K_    4
#define NP1   65            // N_+1
#define POS   520           // M_*NP1
#define FLAT  33280         // 64*M_*NP1
#define ROWS  2048          // B_*L_
#define JD    256           // 4*N_  (pl1 out)
#define J2D   128           // 2*N_  (pl2 out)
#define NPOS  (ROWS*POS)    // 1064960 conv positions

#define SPLIT 8
#define KSL   (FLAT/SPLIT)  // 4160
#define GKC   32            // K per smem chunk
#define NCHUNK (KSL/GKC)    // 130

// output layout: W (512*80) | Theta (2048*64*2) | mu (512*2)
#define OFF_THETA 40960
#define OFF_MU    (40960 + 262144)

// ---------------- scratch (no allocations allowed) ----------------
__device__ float g_H[(size_t)ROWS * FLAT];            // conv output (tf32-rounded)
__device__ float g_Bw[(size_t)JD * FLAT];             // pl1_w tf32-rounded
__device__ float g_Rpart[(size_t)SPLIT * ROWS * JD];  // split-K partials
__device__ float g_Theta[2 * ROWS * N_];              // tr | ti
__device__ float g_pl2T[JD * J2D];                    // pl2_w transposed

// ---------------- helpers: packed f32x2 ----------------
__device__ __forceinline__ unsigned long long pack2(float a, float b) {
    unsigned long long r;
    asm("mov.b64 %0, {%1, %2};" : "=l"(r) : "f"(a), "f"(b));
    return r;
}
__device__ __forceinline__ void fma2(unsigned long long& d,
                                     unsigned long long a,
                                     unsigned long long b) {
    asm("fma.rn.f32x2 %0, %1, %2, %0;" : "+l"(d) : "l"(a), "l"(b));
}
__device__ __forceinline__ float2 unpack2(unsigned long long v) {
    float2 r;
    asm("mov.b64 {%0, %1}, %2;" : "=f"(r.x), "=f"(r.y) : "l"(v));
    return r;
}
__device__ __forceinline__ uint32_t to_tf32(float v) {
    uint32_t u;
    asm("cvt.rna.tf32.f32 %0, %1;" : "=r"(u) : "f"(v));
    return u;
}

// ---------------- helpers: cp.async ----------------
__device__ __forceinline__ uint32_t smem_u32(const void* p) {
    uint32_t a;
    asm("{ .reg .u64 t; cvta.to.shared.u64 t, %1; cvt.u32.u64 %0, t; }" : "=r"(a) : "l"(p));
    return a;
}
#define CPASYNC16(sa, gp)  asm volatile("cp.async.cg.shared.global [%0], [%1], 16;" :: "r"(sa), "l"(gp) : "memory")
#define CP_COMMIT()        asm volatile("cp.async.commit_group;" ::: "memory")
#define CP_WAIT0()         asm volatile("cp.async.wait_group 0;" ::: "memory")
#define CP_WAIT1()         asm volatile("cp.async.wait_group 1;" ::: "memory")

// mma.sync tf32 (family-portable HMMA path; tcgen05 rejected by this toolchain)
__device__ __forceinline__ void mma_tf32(float* d, const uint32_t* a, const uint32_t* b) {
    asm volatile(
        "mma.sync.aligned.m16n8k8.row.col.f32.tf32.tf32.f32 "
        "{%0,%1,%2,%3}, {%4,%5,%6,%7}, {%8,%9}, {%0,%1,%2,%3};"
        : "+f"(d[0]), "+f"(d[1]), "+f"(d[2]), "+f"(d[3])
        : "r"(a[0]), "r"(a[1]), "r"(a[2]), "r"(a[3]), "r"(b[0]), "r"(b[1]));
}

// ---------------- K0: transpose pl2_w (128x256 -> 256x128) ----------------
__global__ void k0_transpose(const float* __restrict__ pl2_w) {
    int idx = blockIdx.x * 256 + threadIdx.x;
    int i = idx >> 7;
    int j = idx & 127;
    g_pl2T[idx] = pl2_w[j * JD + i];
}

// ---------------- K0b: round pl1_w to tf32 -> g_Bw ----------------
__global__ void k0b_round(const float* __restrict__ w) {
    size_t i = ((size_t)blockIdx.x * 256 + threadIdx.x) * 4;
    float4 v = *(const float4*)(w + i);
    v.x = __uint_as_float(to_tf32(v.x));
    v.y = __uint_as_float(to_tf32(v.y));
    v.z = __uint_as_float(to_tf32(v.z));
    v.w = __uint_as_float(to_tf32(v.w));
    *(float4*)(g_Bw + i) = v;
}

// ---------------- K1: fused conv1+conv2 -> g_H ----------------
// 256 threads, 256 positions per CTA. conv1 per-thread -> Hc smem [64][256].
// conv2: register-blocked 4 pos x 16 out per thread, f32x2-duplicated weights
// in smem (broadcast LDS.128), fp32 exact. Output tf32-rounded.
#define K1_WPAD 68                              // ull stride per c-row
#define K1_DYN  (64*256*4 + 64*K1_WPAD*8)       // Hc 64KB + w2d 34.8KB

__global__ void __launch_bounds__(256, 2) k1_conv(
    const float* __restrict__ x,
    const float* __restrict__ w1, const float* __restrict__ b1,
    const float* __restrict__ w2, const float* __restrict__ b2)
{
    extern __shared__ float dsm[];
    float* Hc = dsm;                                             // [64][256]
    unsigned long long* w2d = (unsigned long long*)(dsm + 64 * 256); // [64][K1_WPAD]
    __shared__ __align__(16) float w1s[512];
    __shared__ float b1s[64], b2s[64];

    int t = threadIdx.x;
    for (int i = t; i < 512; i += 256) w1s[i] = w1[i];
    if (t < 64) { b1s[t] = b1[t]; b2s[t] = b2[t]; }
    // w2d[c][o] = dup2(w2[o][c]); coalesced LDG, one-time conflicted STS
    for (int i = t; i < 4096; i += 256) {
        int o = i >> 6, c = i & 63;
        float v = w2[i];
        w2d[c * K1_WPAD + o] = pack2(v, v);
    }
    __syncthreads();

    // -------- conv1: one position per thread --------
    {
        int p = blockIdx.x * 256 + t;
        int bl = p / POS;
        int q  = p - bl * POS;
        const float* xp = x + (size_t)bl * (8 * POS) + q;
        unsigned long long xv2[4];
#pragma unroll
        for (int c = 0; c < 4; c++)
            xv2[c] = pack2(xp[(2 * c) * POS], xp[(2 * c + 1) * POS]);

        const unsigned long long* w1p = (const unsigned long long*)w1s;
#pragma unroll
        for (int i = 0; i < 32; i++) {
            unsigned long long a0 = 0ULL, a1 = 0ULL;
#pragma unroll
            for (int c = 0; c < 4; c++) {
                fma2(a0, xv2[c], w1p[(2 * i) * 4 + c]);
                fma2(a1, xv2[c], w1p[(2 * i + 1) * 4 + c]);
            }
            float2 f0 = unpack2(a0), f1 = unpack2(a1);
            Hc[(2 * i) * 256 + t]     = fmaxf(f0.x + f0.y + b1s[2 * i], 0.f);
            Hc[(2 * i + 1) * 256 + t] = fmaxf(f1.x + f1.y + b1s[2 * i + 1], 0.f);
        }
    }
    __syncthreads();

    // -------- conv2: 4 positions x 16 outputs per thread --------
    int po = t & 63;      // position group: positions 4*po..4*po+3
    int og = t >> 6;      // output group:   outputs 16*og..16*og+15

    unsigned long long acc2[2][16];
#pragma unroll
    for (int j = 0; j < 16; j++) { acc2[0][j] = 0ULL; acc2[1][j] = 0ULL; }

#pragma unroll 8
    for (int c = 0; c < 64; c++) {
        float4 hv = *(const float4*)(Hc + c * 256 + 4 * po);
        unsigned long long h01 = pack2(hv.x, hv.y);
        unsigned long long h23 = pack2(hv.z, hv.w);
        const ulonglong2* wr = (const ulonglong2*)(w2d + c * K1_WPAD + og * 16);
#pragma unroll
        for (int j = 0; j < 8; j++) {
            ulonglong2 w = wr[j];
            fma2(acc2[0][2 * j],     h01, w.x);
            fma2(acc2[1][2 * j],     h23, w.x);
            fma2(acc2[0][2 * j + 1], h01, w.y);
            fma2(acc2[1][2 * j + 1], h23, w.y);
        }
    }

    // epilogue: bias + relu + tf32 round + coalesced float4 stores
    // 4-position chunks never straddle a bl boundary (520 % 4 == 0)
    int p4 = blockIdx.x * 256 + 4 * po;
    int bl2 = p4 / POS;
    int q   = p4 - bl2 * POS;
    float* base = g_H + (size_t)bl2 * FLAT + q;
#pragma unroll
    for (int j = 0; j < 16; j++) {
        int o = og * 16 + j;
        float bb = b2s[o];
        float2 a = unpack2(acc2[0][j]);
        float2 b = unpack2(acc2[1][j]);
        float4 v;
        v.x = __uint_as_float(to_tf32(fmaxf(a.x + bb, 0.f)));
        v.y = __uint_as_float(to_tf32(fmaxf(a.y + bb, 0.f)));
        v.z = __uint_as_float(to_tf32(fmaxf(b.x + bb, 0.f)));
        v.w = __uint_as_float(to_tf32(fmaxf(b.y + bb, 0.f)));
        *(float4*)(base + (size_t)o * POS) = v;
    }
}

// ---------------- K2: mma.sync tf32 split-K GEMM ----------------
// CTA 128x128, Kc=32 double-buffered smem + double-buffered fragments.
// 4 warps (2x2), warp tile 64x64. grid (16 M, 2 N, 8 split)
#define KPAD   36
#define TILE_F (128 * KPAD)
#define TILE_B (TILE_F * 4)
#define SM_DYN (4 * TILE_B)

__device__ __forceinline__ void k2_load_tile(
    int tid, uint32_t sa, uint32_t sb,
    const float* __restrict__ Ab, const float* __restrict__ Bb)
{
#pragma unroll
    for (int j = 0; j < 8; j++) {
        int u = tid + j * 128;
        int r = u >> 3, qd = u & 7;
        uint32_t so = (uint32_t)(r * (KPAD * 4) + qd * 16);
        CPASYNC16(sa + so, Ab + (size_t)r * FLAT + qd * 4);
        CPASYNC16(sb + so, Bb + (size_t)r * FLAT + qd * 4);
    }
}

__global__ void __launch_bounds__(128, 2) k2_mma()
{
    extern __shared__ float smem[];
    uint32_t sbase = smem_u32(smem);
    float* Abuf[2] = { smem,              smem + TILE_F };
    float* Bbuf[2] = { smem + 2 * TILE_F, smem + 3 * TILE_F };
    uint32_t aAddr[2] = { sbase,              sbase + TILE_B };
    uint32_t bAddr[2] = { sbase + 2 * TILE_B, sbase + 3 * TILE_B };

    int tid = threadIdx.x;
    int w   = tid >> 5, lane = tid & 31;
    int g   = lane >> 2, tg = lane & 3;
    int wm  = (w >> 1) * 64;
    int wn  = (w & 1) * 64;

    int row0 = blockIdx.x * 128;
    int col0 = blockIdx.y * 128;
    int sp   = blockIdx.z;
    int k0   = sp * KSL;

    const float* Ab = g_H  + (size_t)row0 * FLAT + k0;
    const float* Bb = g_Bw + (size_t)col0 * FLAT + k0;

    float acc[4][8][4];
#pragma unroll
    for (int i = 0; i < 4; i++)
#pragma unroll
        for (int j = 0; j < 8; j++)
#pragma unroll
            for (int c = 0; c < 4; c++) acc[i][j][c] = 0.f;

    k2_load_tile(tid, aAddr[0], bAddr[0], Ab, Bb);
    CP_COMMIT();

    uint32_t af[2][4][4], bf[2][8][2];

    for (int it = 0; it < NCHUNK; it++) {
        int cur = it & 1;
        if (it + 1 < NCHUNK) {
            k2_load_tile(tid, aAddr[cur ^ 1], bAddr[cur ^ 1],
                         Ab + (size_t)(it + 1) * GKC, Bb + (size_t)(it + 1) * GKC);
            CP_COMMIT();
            CP_WAIT1();
        } else {
            CP_WAIT0();
        }
        __syncthreads();

        const uint32_t* As = (const uint32_t*)Abuf[cur];
        const uint32_t* Bs = (const uint32_t*)Bbuf[cur];

        // prefetch kstep 0 into frag set 0
#pragma unroll
        for (int i = 0; i < 4; i++) {
            int rb = (wm + i * 16 + g) * KPAD;
            af[0][i][0] = As[rb + tg];
            af[0][i][1] = As[rb + 8 * KPAD + tg];
            af[0][i][2] = As[rb + tg + 4];
            af[0][i][3] = As[rb + 8 * KPAD + tg + 4];
        }
#pragma unroll
        for (int j = 0; j < 8; j++) {
            int rb = (wn + j * 8 + g) * KPAD;
            bf[0][j][0] = Bs[rb + tg];
            bf[0][j][1] = Bs[rb + tg + 4];
        }

#pragma unroll
        for (int ks = 0; ks < 4; ks++) {
            int cs = ks & 1;
            if (ks < 3) {
                int kk = (ks + 1) * 8;
#pragma unroll
                for (int i = 0; i < 4; i++) {
                    int rb = (wm + i * 16 + g) * KPAD + kk;
                    af[cs ^ 1][i][0] = As[rb + tg];
                    af[cs ^ 1][i][1] = As[rb + 8 * KPAD + tg];
                    af[cs ^ 1][i][2] = As[rb + tg + 4];
                    af[cs ^ 1][i][3] = As[rb + 8 * KPAD + tg + 4];
                }
#pragma unroll
                for (int j = 0; j < 8; j++) {
                    int rb = (wn + j * 8 + g) * KPAD + kk;
                    bf[cs ^ 1][j][0] = Bs[rb + tg];
                    bf[cs ^ 1][j][1] = Bs[rb + tg + 4];
                }
            }
#pragma unroll
            for (int i = 0; i < 4; i++)
#pragma unroll
                for (int j = 0; j < 8; j++)
                    mma_tf32(acc[i][j], af[cs][i], bf[cs][j]);
        }
        __syncthreads();
    }

    float* Rp = g_Rpart + (size_t)sp * ROWS * JD;
#pragma unroll
    for (int i = 0; i < 4; i++) {
        int r = row0 + wm + i * 16 + g;
#pragma unroll
        for (int j = 0; j < 8; j++) {
            int c = col0 + wn + j * 8 + tg * 2;
            *(float2*)(Rp + (size_t)r * JD + c) =
                make_float2(acc[i][j][0], acc[i][j][1]);
            *(float2*)(Rp + (size_t)(r + 8) * JD + c) =
                make_float2(acc[i][j][2], acc[i][j][3]);
        }
    }
}

// ---------------- K3: split-K reduce + bias/relu + pl2 + Theta ----------------
__global__ void __launch_bounds__(256) k3_epi(
    const float* __restrict__ pl1_b,
    const float* __restrict__ pl2_b,
    float* __restrict__ outTheta)
{
    __shared__ float Hs[8][JD];
    __shared__ float Rls[8][J2D];
    int r0  = blockIdx.x * 8;
    int tid = threadIdx.x;

#pragma unroll
    for (int rr = 0; rr < 8; rr++) {
        size_t base = (size_t)(r0 + rr) * JD + tid;
        float s = 0.f;
#pragma unroll
        for (int sp = 0; sp < SPLIT; sp++)
            s += g_Rpart[(size_t)sp * ROWS * JD + base];
        Hs[rr][tid] = fmaxf(s + pl1_b[tid], 0.f);
    }
    __syncthreads();

    int j = tid & 127;
    int half = tid >> 7;
    float acc[4];
#pragma unroll
    for (int rr = 0; rr < 4; rr++) acc[rr] = pl2_b[j];
#pragma unroll 4
    for (int i = 0; i < JD; i++) {
        float w = g_pl2T[i * J2D + j];
#pragma unroll
        for (int rr = 0; rr < 4; rr++) acc[rr] += Hs[half * 4 + rr][i] * w;
    }
#pragma unroll
    for (int rr = 0; rr < 4; rr++) Rls[half * 4 + rr][j] = acc[rr];
    __syncthreads();

    for (int t = tid; t < 8 * N_; t += 256) {
        int rr = t >> 6, n = t & 63;
        float pr = Rls[rr][n];
        float pi = Rls[rr][n + N_];
        float nm = fmaxf(sqrtf(pr * pr + pi * pi), 1e-12f);
        float tr = pr / nm, ti = pi / nm;
        int r = r0 + rr;
        outTheta[((size_t)r * N_ + n) * 2 + 0] = tr;
        outTheta[((size_t)r * N_ + n) * 2 + 1] = ti;
        g_Theta[r * N_ + n] = tr;
        g_Theta[ROWS * N_ + r * N_ + n] = ti;
    }
}

// ---------------- K4: per-batch H einsums + MLP heads ----------------
__global__ void __launch_bounds__(256) k4_head(
    const float* __restrict__ H_re, const float* __restrict__ H_im,
    const float* __restrict__ ch_re, const float* __restrict__ ch_im,
    const float* __restrict__ b1_w, const float* __restrict__ b1_b,
    const float* __restrict__ b2_w, const float* __restrict__ b2_b,
    const float* __restrict__ b3_w, const float* __restrict__ b3_b,
    const float* __restrict__ p1_w, const float* __restrict__ p1_b,
    const float* __restrict__ p2_w, const float* __restrict__ p2_b,
    float* __restrict__ outW, float* __restrict__ outMu)
{
    int b = blockIdx.x;
    int tid = threadIdx.x;
    __shared__ float trs[256], tis[256];
    __shared__ float cHs[64], W1s[128], P1s[128], W2s[128], W3s[80];
    __shared__ float MUs[2], SCs[1];

    trs[tid] = g_Theta[b * 256 + tid];
    tis[tid] = g_Theta[ROWS * N_ + b * 256 + tid];
    __syncthreads();

    int out = tid >> 3;
    int g   = tid & 7;
    int kk  = out >> 3;
    int mm  = out & 7;
    const float* hre = H_re + (size_t)b * 8192;
    const float* him = H_im + (size_t)b * 8192;
    float s_rr = 0.f, s_ii = 0.f, s_ri = 0.f, s_ir = 0.f;
    for (int t = g; t < 256; t += 8) {
        int n = t >> 2, l = t & 3;
        float tr = trs[l * 64 + n];
        float ti = tis[l * 64 + n];
        int idx = mm * 1024 + n * 16 + l * 4 + kk;
        float hr = hre[idx];
        float hi = him[idx];
        s_rr += hr * tr; s_ii += hi * ti;
        s_ri += hr * ti; s_ir += hi * tr;
    }
#pragma unroll
    for (int off = 4; off; off >>= 1) {
        s_rr += __shfl_down_sync(0xffffffffu, s_rr, off, 8);
        s_ii += __shfl_down_sync(0xffffffffu, s_ii, off, 8);
        s_ri += __shfl_down_sync(0xffffffffu, s_ri, off, 8);
        s_ir += __shfl_down_sync(0xffffffffu, s_ir, off, 8);
    }
    if (g == 0) {
        cHs[kk * 16 + mm]     = s_rr + s_ii + ch_re[(b * 4 + kk) * 8 + mm];
        cHs[kk * 16 + 8 + mm] = s_ri - s_ir + ch_im[(b * 4 + kk) * 8 + mm];
    }
    __syncthreads();

    if (tid < 128) {
        float a = b1_b[tid];
        for (int c = 0; c < 64; c++) a += b1_w[tid * 64 + c] * cHs[c];
        W1s[tid] = fmaxf(a, 0.f);
    } else {
        int jj = tid - 128;
        float a = p1_b[jj];
        for (int c = 0; c < 64; c++) a += p1_w[jj * 64 + c] * cHs[c];
        P1s[jj] = fmaxf(a, 0.f);
    }
    __syncthreads();

    if (tid < 128) {
        float a = b2_b[tid];
        for (int c = 0; c < 128; c++) a += b2_w[tid * 128 + c] * W1s[c];
        W2s[tid] = fmaxf(a, 0.f);
    } else if (tid < 130) {
        int m2 = tid - 128;
        float a = p2_b[m2];
        for (int c = 0; c < 128; c++) a += p2_w[m2 * 128 + c] * P1s[c];
        MUs[m2] = a;
    }
    __syncthreads();

    if (tid < 80) {
        float a = b3_b[tid];
        for (int c = 0; c < 128; c++) a += b3_w[tid * 128 + c] * W2s[c];
        W3s[tid] = a;
    }
    __syncthreads();

    if (tid == 0) {
        float ss = 0.f;
        for (int j = 0; j < 80; j++) ss += W3s[j] * W3s[j];
        float wn = fmaxf(sqrtf(ss), 1e-12f);
        float mx = fmaxf(MUs[0], MUs[1]);
        float e0 = expf(MUs[0] - mx), e1 = expf(MUs[1] - mx);
        float mu0 = e0 / (e0 + e1);
        MUs[0] = mu0;
        MUs[1] = e1 / (e0 + e1);
        SCs[0] = sqrtf(10.0f) * sqrtf(mu0) / wn;
    }
    __syncthreads();

    if (tid < 80) outW[b * 80 + tid] = W3s[tid] * SCs[0];
    if (tid < 2)  outMu[b * 2 + tid] = MUs[tid];
}

// ---------------- launch ----------------
extern "C" void kernel_launch(void* const* d_in, const int* in_sizes, int n_in,
                              void* d_out, int out_size)
{
    const float* x       = (const float*)d_in[0];
    const float* H_re    = (const float*)d_in[1];
    const float* H_im    = (const float*)d_in[2];
    const float* ch_re   = (const float*)d_in[3];
    const float* ch_im   = (const float*)d_in[4];
    const float* conv1_w = (const float*)d_in[5];
    const float* conv1_b = (const float*)d_in[6];
    const float* conv2_w = (const float*)d_in[7];
    const float* conv2_b = (const float*)d_in[8];
    const float* pl1_w   = (const float*)d_in[9];
    const float* pl1_b   = (const float*)d_in[10];
    const float* pl2_w   = (const float*)d_in[11];
    const float* pl2_b   = (const float*)d_in[12];
    const float* b1_w    = (const float*)d_in[13];
    const float* b1_b    = (const float*)d_in[14];
    const float* b2_w    = (const float*)d_in[15];
    const float* b2_b    = (const float*)d_in[16];
    const float* b3_w    = (const float*)d_in[17];
    const float* b3_b    = (const float*)d_in[18];
    const float* p1_w    = (const float*)d_in[19];
    const float* p1_b    = (const float*)d_in[20];
    const float* p2_w    = (const float*)d_in[21];
    const float* p2_b    = (const float*)d_in[22];

    float* out      = (float*)d_out;
    float* outW     = out;
    float* outTheta = out + OFF_THETA;
    float* outMu    = out + OFF_MU;

    cudaFuncSetAttribute(k1_conv, cudaFuncAttributeMaxDynamicSharedMemorySize, K1_DYN);
    cudaFuncSetAttribute(k2_mma, cudaFuncAttributeMaxDynamicSharedMemorySize, SM_DYN);

    k0_transpose<<<128, 256>>>(pl2_w);
    k0b_round<<<(JD * FLAT) / (256 * 4), 256>>>(pl1_w);
    k1_conv<<<NPOS / 256, 256, K1_DYN>>>(x, conv1_w, conv1_b, conv2_w, conv2_b);
    dim3 g2(ROWS / 128, JD / 128, SPLIT);
    k2_mma<<<g2, 128, SM_DYN>>>();
    k3_epi<<<ROWS / 8, 256>>>(pl1_b, pl2_b, outTheta);
    k4_head<<<B_, 256>>>(H_re, H_im, ch_re, ch_im,
                         b1_w, b1_b, b2_w, b2_b, b3_w, b3_b,
                         p1_w, p1_b, p2_w, p2_b, outW, outMu);
}

// round 6
// speedup vs baseline: 2.3800x; 1.0292x over previous
#include <cuda_runtime.h>
#include <cuda_bf16.h>
#include <math.h>
#include <stdint.h>

// ---------------- problem constants ----------------
#define B_    512
#define L_    4
#define M_    8
#define N_    64
#define NP1   65
#define POS   520           // M_*NP1
#define FLAT  33280         // 64*POS
#define ROWS  2048          // B_*L_
#define JD    256           // pl1 out
#define J2D   128           // pl2 out

#define SPLIT 8             // q-splits
#define QPC   65            // q per CTA (520/8)

// output layout: W (512*80) | Theta (2048*64*2) | mu (512*2)
#define OFF_THETA 40960
#define OFF_MU    (40960 + 262144)

// ---------------- scratch ----------------
__device__ float g_Bw[(size_t)FLAT * JD];             // permuted pl1_w: [q][o][j] (tf32)
__device__ float g_xT[(size_t)ROWS * POS * 8];        // x transposed: [bl][q][c] (fp32)
__device__ float g_Rpart[(size_t)SPLIT * ROWS * JD];  // split-K partials
__device__ float g_Theta[2 * ROWS * N_];              // tr | ti
__device__ float g_pl2T[JD * J2D];                    // pl2_w transposed

// ---------------- helpers ----------------
__device__ __forceinline__ uint32_t to_tf32(float v) {
    uint32_t u;
    asm("cvt.rna.tf32.f32 %0, %1;" : "=r"(u) : "f"(v));
    return u;
}
// Dekker split: v = hi + lo with hi, lo representable in tf32
__device__ __forceinline__ void split_tf32(uint32_t v, uint32_t& hi, uint32_t& lo) {
    float f = __uint_as_float(v);
    uint32_t h = to_tf32(f);
    float fl = f - __uint_as_float(h);
    hi = h;
    lo = to_tf32(fl);
}
__device__ __forceinline__ uint32_t smem_u32(const void* p) {
    uint32_t a;
    asm("{ .reg .u64 t; cvta.to.shared.u64 t, %1; cvt.u32.u64 %0, t; }" : "=r"(a) : "l"(p));
    return a;
}
#define CPASYNC16(sa, gp)  asm volatile("cp.async.cg.shared.global [%0], [%1], 16;" :: "r"(sa), "l"(gp) : "memory")
#define CP_COMMIT()        asm volatile("cp.async.commit_group;" ::: "memory")
#define CP_WAIT0()         asm volatile("cp.async.wait_group 0;" ::: "memory")

__device__ __forceinline__ void mma_tf32(float* d, const uint32_t* a, const uint32_t* b) {
    asm volatile(
        "mma.sync.aligned.m16n8k8.row.col.f32.tf32.tf32.f32 "
        "{%0,%1,%2,%3}, {%4,%5,%6,%7}, {%8,%9}, {%0,%1,%2,%3};"
        : "+f"(d[0]), "+f"(d[1]), "+f"(d[2]), "+f"(d[3])
        : "r"(a[0]), "r"(a[1]), "r"(a[2]), "r"(a[3]), "r"(b[0]), "r"(b[1]));
}

// ---------------- K0: transpose pl2_w (128x256 -> 256x128) ----------------
__global__ void k0_transpose(const float* __restrict__ pl2_w) {
    int idx = blockIdx.x * 256 + threadIdx.x;
    int i = idx >> 7;
    int j = idx & 127;
    g_pl2T[idx] = pl2_w[j * JD + i];
}

// ---------------- K0x: x -> xq[bl][q][c], raw fp32 ----------------
__global__ void __launch_bounds__(256) k0x(const float* __restrict__ x) {
    int tl = blockIdx.x * 256 + threadIdx.x;   // over ROWS*POS
    int bl = tl / POS;
    int q  = tl - bl * POS;
    const float* xp = x + (size_t)bl * (8 * POS) + q;
    float4 v0, v1;
    v0.x = xp[0 * POS]; v0.y = xp[1 * POS]; v0.z = xp[2 * POS]; v0.w = xp[3 * POS];
    v1.x = xp[4 * POS]; v1.y = xp[5 * POS]; v1.z = xp[6 * POS]; v1.w = xp[7 * POS];
    float4* dst = (float4*)(g_xT + (size_t)tl * 8);
    dst[0] = v0;
    dst[1] = v1;
}

// ---------------- K0p: permute pl1_w [j][k] -> Bp[q][o][j], tf32 ----------
__global__ void __launch_bounds__(256) k0p(const float* __restrict__ pl1_w) {
    __shared__ float ts[32][33];
    int k0 = blockIdx.x * 32;
    int j0 = blockIdx.y * 32;
    int tx = threadIdx.x & 31;
    int ty = threadIdx.x >> 5;    // 0..7
#pragma unroll
    for (int r = 0; r < 4; r++) {
        int j = j0 + ty + r * 8;
        ts[ty + r * 8][tx] = pl1_w[(size_t)j * FLAT + k0 + tx];
    }
    __syncthreads();
#pragma unroll
    for (int r = 0; r < 4; r++) {
        int k = k0 + ty + r * 8;
        int o = k / POS;
        int q = k - o * POS;
        g_Bw[((size_t)q * 64 + o) * JD + j0 + tx] =
            __uint_as_float(to_tf32(ts[tx][ty + r * 8]));
    }
}

// ---------------- KF: fused conv1+conv2+pl1 GEMM (tensor cores) -----------
// Convs computed with 3-term split-tf32 (~fp32 exact); main GEMM 1-pass tf32.
#define BS_STRIDE 264
#define BS_FLOATS (64 * BS_STRIDE)     // 16896
#define AS_STRIDE 68
#define AS_FLOATS (128 * AS_STRIDE)    // 8704
#define XS_STRIDE 12
#define XS_FLOATS (128 * XS_STRIDE)    // 1536
#define W1T_STRIDE 72
#define W2T_STRIDE 72
#define KF_FLOATS (2*BS_FLOATS + AS_FLOATS + 2*XS_FLOATS + 2*8*W1T_STRIDE + 2*64*W2T_STRIDE + 128)
#define KF_DYN    (KF_FLOATS * 4)      // 224,256 B

__device__ __forceinline__ void kf_load_chunk(
    uint32_t bsA, uint32_t xsA, int q, int row0, int tid)
{
    const float* Bq = g_Bw + (size_t)q * (64 * JD);
#pragma unroll
    for (int k = 0; k < 16; k++) {
        int u = tid + k * 256;
        int o = u >> 6, jq = u & 63;
        CPASYNC16(bsA + (uint32_t)(o * BS_STRIDE + jq * 4) * 4, Bq + (size_t)u * 4);
    }
    {
        int r = tid >> 1, half = tid & 1;
        const float* src = g_xT + ((size_t)(row0 + r) * POS + q) * 8 + half * 4;
        CPASYNC16(xsA + (uint32_t)(r * XS_STRIDE + half * 4) * 4, src);
    }
}

__global__ void __launch_bounds__(256, 1) kF(
    const float* __restrict__ w1, const float* __restrict__ b1,
    const float* __restrict__ w2, const float* __restrict__ b2)
{
    extern __shared__ float sm[];
    float* BsF[2] = { sm, sm + BS_FLOATS };
    float* AsF    = sm + 2 * BS_FLOATS;
    float* W1Th   = AsF + AS_FLOATS + 2 * XS_FLOATS;
    float* W1Tl   = W1Th + 8 * W1T_STRIDE;
    float* W2Th   = W1Tl + 8 * W1T_STRIDE;
    float* W2Tl   = W2Th + 64 * W2T_STRIDE;
    float* b1s    = W2Tl + 64 * W2T_STRIDE;
    float* b2s    = b1s + 64;

    uint32_t sbase = smem_u32(sm);
    uint32_t bsA[2] = { sbase, sbase + BS_FLOATS * 4 };
    uint32_t xsA[2] = { sbase + (uint32_t)(2 * BS_FLOATS + AS_FLOATS) * 4,
                        sbase + (uint32_t)(2 * BS_FLOATS + AS_FLOATS + XS_FLOATS) * 4 };
    const uint32_t* XsU[2] = { (const uint32_t*)(AsF + AS_FLOATS),
                               (const uint32_t*)(AsF + AS_FLOATS + XS_FLOATS) };

    int tid = threadIdx.x;
    int w = tid >> 5, lane = tid & 31, g = lane >> 2, tg = lane & 3;
    int row0 = blockIdx.x * 128;
    int sp = blockIdx.y;
    int q0 = sp * QPC;

    // weights split hi/lo (tf32 pair), biases fp32
    for (int i = tid; i < 512; i += 256) {
        uint32_t hi, lo;
        split_tf32(__float_as_uint(w1[i]), hi, lo);
        W1Th[(i & 7) * W1T_STRIDE + (i >> 3)] = __uint_as_float(hi);
        W1Tl[(i & 7) * W1T_STRIDE + (i >> 3)] = __uint_as_float(lo);
    }
    for (int i = tid; i < 4096; i += 256) {
        uint32_t hi, lo;
        split_tf32(__float_as_uint(w2[i]), hi, lo);
        W2Th[(i & 63) * W2T_STRIDE + (i >> 6)] = __uint_as_float(hi);
        W2Tl[(i & 63) * W2T_STRIDE + (i >> 6)] = __uint_as_float(lo);
    }
    if (tid < 64) { b1s[tid] = b1[tid]; b2s[tid] = b2[tid]; }

    kf_load_chunk(bsA[0], xsA[0], q0, row0, tid);
    CP_COMMIT();

    float acc[4][8][4];
#pragma unroll
    for (int i = 0; i < 4; i++)
#pragma unroll
        for (int j = 0; j < 8; j++)
#pragma unroll
            for (int c = 0; c < 4; c++) acc[i][j][c] = 0.f;

    int wm = (w >> 2) * 64;
    int wn = (w & 3) * 64;
    int m1 = w * 16;

    const uint32_t* W1h = (const uint32_t*)W1Th;
    const uint32_t* W1l = (const uint32_t*)W1Tl;
    const uint32_t* W2h = (const uint32_t*)W2Th;
    const uint32_t* W2l = (const uint32_t*)W2Tl;
    const uint32_t* AuC = (const uint32_t*)AsF;

    for (int it = 0; it < QPC; it++) {
        int cur = it & 1;
        CP_WAIT0();
        __syncthreads();

        if (it + 1 < QPC) {
            kf_load_chunk(bsA[cur ^ 1], xsA[cur ^ 1], q0 + it + 1, row0, tid);
            CP_COMMIT();
        }

        // -------- conv1: C1[16x64] per warp = X[16x8] @ W1T, split-tf32 ----
        {
            const uint32_t* Xc = XsU[cur];
            uint32_t a[4], ah[4], al[4];
            a[0] = Xc[(m1 + g) * XS_STRIDE + tg];
            a[1] = Xc[(m1 + g + 8) * XS_STRIDE + tg];
            a[2] = Xc[(m1 + g) * XS_STRIDE + tg + 4];
            a[3] = Xc[(m1 + g + 8) * XS_STRIDE + tg + 4];
#pragma unroll
            for (int t = 0; t < 4; t++) split_tf32(a[t], ah[t], al[t]);
#pragma unroll
            for (int nt = 0; nt < 8; nt++) {
                uint32_t bh[2] = { W1h[tg * W1T_STRIDE + nt * 8 + g],
                                   W1h[(tg + 4) * W1T_STRIDE + nt * 8 + g] };
                uint32_t blo[2] = { W1l[tg * W1T_STRIDE + nt * 8 + g],
                                    W1l[(tg + 4) * W1T_STRIDE + nt * 8 + g] };
                float c[4] = { 0.f, 0.f, 0.f, 0.f };
                mma_tf32(c, ah, bh);
                mma_tf32(c, al, bh);
                mma_tf32(c, ah, blo);
                float bb0 = b1s[nt * 8 + 2 * tg], bb1 = b1s[nt * 8 + 2 * tg + 1];
                float2 p0, p1;
                p0.x = fmaxf(c[0] + bb0, 0.f);   // keep fp32 (no rounding)
                p0.y = fmaxf(c[1] + bb1, 0.f);
                p1.x = fmaxf(c[2] + bb0, 0.f);
                p1.y = fmaxf(c[3] + bb1, 0.f);
                *(float2*)&AsF[(m1 + g) * AS_STRIDE + nt * 8 + 2 * tg] = p0;
                *(float2*)&AsF[(m1 + g + 8) * AS_STRIDE + nt * 8 + 2 * tg] = p1;
            }
        }
        __syncthreads();

        // -------- conv2: S[16x64] per warp = h1[16x64] @ W2T, split-tf32 ---
        float s[8][4];
#pragma unroll
        for (int nt = 0; nt < 8; nt++)
#pragma unroll
            for (int c = 0; c < 4; c++) s[nt][c] = 0.f;
#pragma unroll
        for (int ks = 0; ks < 8; ks++) {
            int k0 = ks * 8;
            uint32_t a[4], ah[4], al[4];
            a[0] = AuC[(m1 + g) * AS_STRIDE + k0 + tg];
            a[1] = AuC[(m1 + g + 8) * AS_STRIDE + k0 + tg];
            a[2] = AuC[(m1 + g) * AS_STRIDE + k0 + tg + 4];
            a[3] = AuC[(m1 + g + 8) * AS_STRIDE + k0 + tg + 4];
#pragma unroll
            for (int t = 0; t < 4; t++) split_tf32(a[t], ah[t], al[t]);
#pragma unroll
            for (int nt = 0; nt < 8; nt++) {
                uint32_t bh[2] = { W2h[(k0 + tg) * W2T_STRIDE + nt * 8 + g],
                                   W2h[(k0 + tg + 4) * W2T_STRIDE + nt * 8 + g] };
                uint32_t blo[2] = { W2l[(k0 + tg) * W2T_STRIDE + nt * 8 + g],
                                    W2l[(k0 + tg + 4) * W2T_STRIDE + nt * 8 + g] };
                mma_tf32(s[nt], ah, bh);
                mma_tf32(s[nt], al, bh);
                mma_tf32(s[nt], ah, blo);
            }
        }
        __syncthreads();

        // store S -> As (bias + relu + tf32 round, matching R4 numerics)
#pragma unroll
        for (int nt = 0; nt < 8; nt++) {
            float bb0 = b2s[nt * 8 + 2 * tg], bb1 = b2s[nt * 8 + 2 * tg + 1];
            float2 p0, p1;
            p0.x = __uint_as_float(to_tf32(fmaxf(s[nt][0] + bb0, 0.f)));
            p0.y = __uint_as_float(to_tf32(fmaxf(s[nt][1] + bb1, 0.f)));
            p1.x = __uint_as_float(to_tf32(fmaxf(s[nt][2] + bb0, 0.f)));
            p1.y = __uint_as_float(to_tf32(fmaxf(s[nt][3] + bb1, 0.f)));
            *(float2*)&AsF[(m1 + g) * AS_STRIDE + nt * 8 + 2 * tg] = p0;
            *(float2*)&AsF[(m1 + g + 8) * AS_STRIDE + nt * 8 + 2 * tg] = p1;
        }
        __syncthreads();

        // -------- main: acc += A[128x64] @ Bq[64x256], 1-pass tf32 ---------
        {
            const uint32_t* Bu = (const uint32_t*)BsF[cur];
#pragma unroll
            for (int ks = 0; ks < 8; ks++) {
                int k0 = ks * 8;
                uint32_t af[4][4];
#pragma unroll
                for (int im = 0; im < 4; im++) {
                    int rb = (wm + im * 16 + g) * AS_STRIDE + k0;
                    af[im][0] = AuC[rb + tg];
                    af[im][1] = AuC[rb + 8 * AS_STRIDE + tg];
                    af[im][2] = AuC[rb + tg + 4];
                    af[im][3] = AuC[rb + 8 * AS_STRIDE + tg + 4];
                }
                uint32_t bfr[8][2];
#pragma unroll
                for (int jn = 0; jn < 8; jn++) {
                    int cb = (k0 + tg) * BS_STRIDE + wn + jn * 8 + g;
                    bfr[jn][0] = Bu[cb];
                    bfr[jn][1] = Bu[cb + 4 * BS_STRIDE];
                }
#pragma unroll
                for (int im = 0; im < 4; im++)
#pragma unroll
                    for (int jn = 0; jn < 8; jn++)
                        mma_tf32(acc[im][jn], af[im], bfr[jn]);
            }
        }
    }

    float* Rp = g_Rpart + (size_t)sp * ROWS * JD;
#pragma unroll
    for (int im = 0; im < 4; im++) {
        int r = row0 + wm + im * 16 + g;
#pragma unroll
        for (int jn = 0; jn < 8; jn++) {
            int c = wn + jn * 8 + tg * 2;
            *(float2*)(Rp + (size_t)r * JD + c) =
                make_float2(acc[im][jn][0], acc[im][jn][1]);
            *(float2*)(Rp + (size_t)(r + 8) * JD + c) =
                make_float2(acc[im][jn][2], acc[im][jn][3]);
        }
    }
}

// ---------------- K3: split-K reduce + bias/relu + pl2 + Theta ----------------
__global__ void __launch_bounds__(256) k3_epi(
    const float* __restrict__ pl1_b,
    const float* __restrict__ pl2_b,
    float* __restrict__ outTheta)
{
    __shared__ float Hs[8][JD];
    __shared__ float Rls[8][J2D];
    int r0  = blockIdx.x * 8;
    int tid = threadIdx.x;

#pragma unroll
    for (int rr = 0; rr < 8; rr++) {
        size_t base = (size_t)(r0 + rr) * JD + tid;
        float s = 0.f;
#pragma unroll
        for (int sp = 0; sp < SPLIT; sp++)
            s += g_Rpart[(size_t)sp * ROWS * JD + base];
        Hs[rr][tid] = fmaxf(s + pl1_b[tid], 0.f);
    }
    __syncthreads();

    int j = tid & 127;
    int half = tid >> 7;
    float acc[4];
#pragma unroll
    for (int rr = 0; rr < 4; rr++) acc[rr] = pl2_b[j];
#pragma unroll 4
    for (int i = 0; i < JD; i++) {
        float w = g_pl2T[i * J2D + j];
#pragma unroll
        for (int rr = 0; rr < 4; rr++) acc[rr] += Hs[half * 4 + rr][i] * w;
    }
#pragma unroll
    for (int rr = 0; rr < 4; rr++) Rls[half * 4 + rr][j] = acc[rr];
    __syncthreads();

    for (int t = tid; t < 8 * N_; t += 256) {
        int rr = t >> 6, n = t & 63;
        float pr = Rls[rr][n];
        float pi = Rls[rr][n + N_];
        float nm = fmaxf(sqrtf(pr * pr + pi * pi), 1e-12f);
        float tr = pr / nm, ti = pi / nm;
        int r = r0 + rr;
        outTheta[((size_t)r * N_ + n) * 2 + 0] = tr;
        outTheta[((size_t)r * N_ + n) * 2 + 1] = ti;
        g_Theta[r * N_ + n] = tr;
        g_Theta[ROWS * N_ + r * N_ + n] = ti;
    }
}

// ---------------- K4: per-batch H einsums + MLP heads ----------------
__global__ void __launch_bounds__(256) k4_head(
    const float* __restrict__ H_re, const float* __restrict__ H_im,
    const float* __restrict__ ch_re, const float* __restrict__ ch_im,
    const float* __restrict__ b1_w, const float* __restrict__ b1_b,
    const float* __restrict__ b2_w, const float* __restrict__ b2_b,
    const float* __restrict__ b3_w, const float* __restrict__ b3_b,
    const float* __restrict__ p1_w, const float* __restrict__ p1_b,
    const float* __restrict__ p2_w, const float* __restrict__ p2_b,
    float* __restrict__ outW, float* __restrict__ outMu)
{
    int b = blockIdx.x;
    int tid = threadIdx.x;
    __shared__ float trs[256], tis[256];
    __shared__ float cHs[64], W1s[128], P1s[128], W2s[128], W3s[80];
    __shared__ float MUs[2], SCs[1];

    trs[tid] = g_Theta[b * 256 + tid];
    tis[tid] = g_Theta[ROWS * N_ + b * 256 + tid];
    __syncthreads();

    int out = tid >> 3;
    int g   = tid & 7;
    int kk  = out >> 3;
    int mm  = out & 7;
    const float* hre = H_re + (size_t)b * 8192;
    const float* him = H_im + (size_t)b * 8192;
    float s_rr = 0.f, s_ii = 0.f, s_ri = 0.f, s_ir = 0.f;
    for (int t = g; t < 256; t += 8) {
        int n = t >> 2, l = t & 3;
        float tr = trs[l * 64 + n];
        float ti = tis[l * 64 + n];
        int idx = mm * 1024 + n * 16 + l * 4 + kk;
        float hr = hre[idx];
        float hi = him[idx];
        s_rr += hr * tr; s_ii += hi * ti;
        s_ri += hr * ti; s_ir += hi * tr;
    }
#pragma unroll
    for (int off = 4; off; off >>= 1) {
        s_rr += __shfl_down_sync(0xffffffffu, s_rr, off, 8);
        s_ii += __shfl_down_sync(0xffffffffu, s_ii, off, 8);
        s_ri += __shfl_down_sync(0xffffffffu, s_ri, off, 8);
        s_ir += __shfl_down_sync(0xffffffffu, s_ir, off, 8);
    }
    if (g == 0) {
        cHs[kk * 16 + mm]     = s_rr + s_ii + ch_re[(b * 4 + kk) * 8 + mm];
        cHs[kk * 16 + 8 + mm] = s_ri - s_ir + ch_im[(b * 4 + kk) * 8 + mm];
    }
    __syncthreads();

    if (tid < 128) {
        float a = b1_b[tid];
        for (int c = 0; c < 64; c++) a += b1_w[tid * 64 + c] * cHs[c];
        W1s[tid] = fmaxf(a, 0.f);
    } else {
        int jj = tid - 128;
        float a = p1_b[jj];
        for (int c = 0; c < 64; c++) a += p1_w[jj * 64 + c] * cHs[c];
        P1s[jj] = fmaxf(a, 0.f);
    }
    __syncthreads();

    if (tid < 128) {
        float a = b2_b[tid];
        for (int c = 0; c < 128; c++) a += b2_w[tid * 128 + c] * W1s[c];
        W2s[tid] = fmaxf(a, 0.f);
    } else if (tid < 130) {
        int m2 = tid - 128;
        float a = p2_b[m2];
        for (int c = 0; c < 128; c++) a += p2_w[m2 * 128 + c] * P1s[c];
        MUs[m2] = a;
    }
    __syncthreads();

    if (tid < 80) {
        float a = b3_b[tid];
        for (int c = 0; c < 128; c++) a += b3_w[tid * 128 + c] * W2s[c];
        W3s[tid] = a;
    }
    __syncthreads();

    if (tid == 0) {
        float ss = 0.f;
        for (int j = 0; j < 80; j++) ss += W3s[j] * W3s[j];
        float wn = fmaxf(sqrtf(ss), 1e-12f);
        float mx = fmaxf(MUs[0], MUs[1]);
        float e0 = expf(MUs[0] - mx), e1 = expf(MUs[1] - mx);
        float mu0 = e0 / (e0 + e1);
        MUs[0] = mu0;
        MUs[1] = e1 / (e0 + e1);
        SCs[0] = sqrtf(10.0f) * sqrtf(mu0) / wn;
    }
    __syncthreads();

    if (tid < 80) outW[b * 80 + tid] = W3s[tid] * SCs[0];
    if (tid < 2)  outMu[b * 2 + tid] = MUs[tid];
}

// ---------------- launch ----------------
extern "C" void kernel_launch(void* const* d_in, const int* in_sizes, int n_in,
                              void* d_out, int out_size)
{
    const float* x       = (const float*)d_in[0];
    const float* H_re    = (const float*)d_in[1];
    const float* H_im    = (const float*)d_in[2];
    const float* ch_re   = (const float*)d_in[3];
    const float* ch_im   = (const float*)d_in[4];
    const float* conv1_w = (const float*)d_in[5];
    const float* conv1_b = (const float*)d_in[6];
    const float* conv2_w = (const float*)d_in[7];
    const float* conv2_b = (const float*)d_in[8];
    const float* pl1_w   = (const float*)d_in[9];
    const float* pl1_b   = (const float*)d_in[10];
    const float* pl2_w   = (const float*)d_in[11];
    const float* pl2_b   = (const float*)d_in[12];
    const float* b1_w    = (const float*)d_in[13];
    const float* b1_b    = (const float*)d_in[14];
    const float* b2_w    = (const float*)d_in[15];
    const float* b2_b    = (const float*)d_in[16];
    const float* b3_w    = (const float*)d_in[17];
    const float* b3_b    = (const float*)d_in[18];
    const float* p1_w    = (const float*)d_in[19];
    const float* p1_b    = (const float*)d_in[20];
    const float* p2_w    = (const float*)d_in[21];
    const float* p2_b    = (const float*)d_in[22];

    float* out      = (float*)d_out;
    float* outW     = out;
    float* outTheta = out + OFF_THETA;
    float* outMu    = out + OFF_MU;

    cudaFuncSetAttribute(kF, cudaFuncAttributeMaxDynamicSharedMemorySize, KF_DYN);

    k0_transpose<<<128, 256>>>(pl2_w);
    k0x<<<(ROWS * POS) / 256, 256>>>(x);
    dim3 gp(FLAT / 32, JD / 32);
    k0p<<<gp, 256>>>(pl1_w);
    dim3 gf(ROWS / 128, SPLIT);
    kF<<<gf, 256, KF_DYN>>>(conv1_w, conv1_b, conv2_w, conv2_b);
    k3_epi<<<ROWS / 8, 256>>>(pl1_b, pl2_b, outTheta);
    k4_head<<<B_, 256>>>(H_re, H_im, ch_re, ch_im,
                         b1_w, b1_b, b2_w, b2_b, b3_w, b3_b,
                         p1_w, p1_b, p2_w, p2_b, outW, outMu);
}

// round 7
// speedup vs baseline: 2.8033x; 1.1779x over previous
#include <cuda_runtime.h>
#include <cuda_bf16.h>
#include <math.h>
#include <stdint.h>

// ---------------- problem constants ----------------
#define B_    512
#define L_    4
#define M_    8
#define N_    64
#define NP1   65
#define POS   520           // M_*NP1
#define FLAT  33280         // 64*POS
#define ROWS  2048          // B_*L_
#define JD    256           // pl1 out
#define J2D   128           // pl2 out

#define SPLIT 9             // q-splits (144 CTAs on 148 SMs)

// output layout: W (512*80) | Theta (2048*64*2) | mu (512*2)
#define OFF_THETA 40960
#define OFF_MU    (40960 + 262144)

// ---------------- scratch ----------------
__device__ float g_Bw[(size_t)FLAT * JD];             // permuted pl1_w: [q][o][j] (tf32)
__device__ float g_xT[(size_t)ROWS * POS * 8];        // x transposed: [bl][q][c] (fp32)
__device__ float g_Rpart[(size_t)SPLIT * ROWS * JD];  // split-K partials
__device__ float g_Theta[2 * ROWS * N_];              // tr | ti
__device__ float g_pl2T[JD * J2D];                    // pl2_w transposed

// ---------------- helpers ----------------
__device__ __forceinline__ uint32_t to_tf32(float v) {
    uint32_t u;
    asm("cvt.rna.tf32.f32 %0, %1;" : "=r"(u) : "f"(v));
    return u;
}
__device__ __forceinline__ void split_tf32(uint32_t v, uint32_t& hi, uint32_t& lo) {
    float f = __uint_as_float(v);
    uint32_t h = to_tf32(f);
    float fl = f - __uint_as_float(h);
    hi = h;
    lo = to_tf32(fl);
}
__device__ __forceinline__ uint32_t pack_bf16x2(float a, float b) {
    __nv_bfloat162 h = __floats2bfloat162_rn(a, b);   // x=a (low), y=b (high)
    return *(uint32_t*)&h;
}
__device__ __forceinline__ uint32_t smem_u32(const void* p) {
    uint32_t a;
    asm("{ .reg .u64 t; cvta.to.shared.u64 t, %1; cvt.u32.u64 %0, t; }" : "=r"(a) : "l"(p));
    return a;
}
#define CPASYNC16(sa, gp)  asm volatile("cp.async.cg.shared.global [%0], [%1], 16;" :: "r"(sa), "l"(gp) : "memory")
#define CP_COMMIT()        asm volatile("cp.async.commit_group;" ::: "memory")
#define CP_WAIT0()         asm volatile("cp.async.wait_group 0;" ::: "memory")

__device__ __forceinline__ void mma_tf32(float* d, const uint32_t* a, const uint32_t* b) {
    asm volatile(
        "mma.sync.aligned.m16n8k8.row.col.f32.tf32.tf32.f32 "
        "{%0,%1,%2,%3}, {%4,%5,%6,%7}, {%8,%9}, {%0,%1,%2,%3};"
        : "+f"(d[0]), "+f"(d[1]), "+f"(d[2]), "+f"(d[3])
        : "r"(a[0]), "r"(a[1]), "r"(a[2]), "r"(a[3]), "r"(b[0]), "r"(b[1]));
}
__device__ __forceinline__ void mma_bf16(float* d, const uint32_t* a, const uint32_t* b) {
    asm volatile(
        "mma.sync.aligned.m16n8k16.row.col.f32.bf16.bf16.f32 "
        "{%0,%1,%2,%3}, {%4,%5,%6,%7}, {%8,%9}, {%0,%1,%2,%3};"
        : "+f"(d[0]), "+f"(d[1]), "+f"(d[2]), "+f"(d[3])
        : "r"(a[0]), "r"(a[1]), "r"(a[2]), "r"(a[3]), "r"(b[0]), "r"(b[1]));
}

// ---------------- K0: transpose pl2_w (128x256 -> 256x128) ----------------
__global__ void k0_transpose(const float* __restrict__ pl2_w) {
    int idx = blockIdx.x * 256 + threadIdx.x;
    int i = idx >> 7;
    int j = idx & 127;
    g_pl2T[idx] = pl2_w[j * JD + i];
}

// ---------------- K0x: x -> xq[bl][q][c], raw fp32 ----------------
__global__ void __launch_bounds__(256) k0x(const float* __restrict__ x) {
    int tl = blockIdx.x * 256 + threadIdx.x;
    int bl = tl / POS;
    int q  = tl - bl * POS;
    const float* xp = x + (size_t)bl * (8 * POS) + q;
    float4 v0, v1;
    v0.x = xp[0 * POS]; v0.y = xp[1 * POS]; v0.z = xp[2 * POS]; v0.w = xp[3 * POS];
    v1.x = xp[4 * POS]; v1.y = xp[5 * POS]; v1.z = xp[6 * POS]; v1.w = xp[7 * POS];
    float4* dst = (float4*)(g_xT + (size_t)tl * 8);
    dst[0] = v0;
    dst[1] = v1;
}

// ---------------- K0p: permute pl1_w [j][k] -> Bp[q][o][j], tf32 ----------
__global__ void __launch_bounds__(256) k0p(const float* __restrict__ pl1_w) {
    __shared__ float ts[32][33];
    int k0 = blockIdx.x * 32;
    int j0 = blockIdx.y * 32;
    int tx = threadIdx.x & 31;
    int ty = threadIdx.x >> 5;
#pragma unroll
    for (int r = 0; r < 4; r++) {
        int j = j0 + ty + r * 8;
        ts[ty + r * 8][tx] = pl1_w[(size_t)j * FLAT + k0 + tx];
    }
    __syncthreads();
#pragma unroll
    for (int r = 0; r < 4; r++) {
        int k = k0 + ty + r * 8;
        int o = k / POS;
        int q = k - o * POS;
        g_Bw[((size_t)q * 64 + o) * JD + j0 + tx] =
            __uint_as_float(to_tf32(ts[tx][ty + r * 8]));
    }
}

// ---------------- KF: fused conv1+conv2+pl1 GEMM ----------------
// conv1 tf32x3, conv2 bf16x3, main tf32 1-pass. h1 kept as packed bf16
// hi/lo pairs aliasing the A (tf32) region.
#define BS_STRIDE 264
#define BS_FLOATS (64 * BS_STRIDE)       // 16896
#define AS_STRIDE 68                     // fp32 A for main GEMM
#define HP        36                     // h1 packed stride (uints per row)
#define AREG_W    (2 * 128 * HP)         // 9216 words (h1 hi + lo); >= 128*68
#define XS_STRIDE 12
#define XS_FLOATS (128 * XS_STRIDE)      // 1536
#define W1T_STRIDE 72
#define W2P_STRIDE 72                    // uints per kpair row
#define KF_WORDS (2*BS_FLOATS + AREG_W + 2*XS_FLOATS + 2*8*W1T_STRIDE + 2*32*W2P_STRIDE + 128)
#define KF_DYN   (KF_WORDS * 4)          // 207,872 B

__device__ __forceinline__ void kf_load_chunk(
    uint32_t bsA, uint32_t xsA, int q, int row0, int tid)
{
    const float* Bq = g_Bw + (size_t)q * (64 * JD);
#pragma unroll
    for (int k = 0; k < 16; k++) {
        int u = tid + k * 256;
        int o = u >> 6, jq = u & 63;
        CPASYNC16(bsA + (uint32_t)(o * BS_STRIDE + jq * 4) * 4, Bq + (size_t)u * 4);
    }
    {
        int r = tid >> 1, half = tid & 1;
        const float* src = g_xT + ((size_t)(row0 + r) * POS + q) * 8 + half * 4;
        CPASYNC16(xsA + (uint32_t)(r * XS_STRIDE + half * 4) * 4, src);
    }
}

__global__ void __launch_bounds__(256, 1) kF(
    const float* __restrict__ w1, const float* __restrict__ b1,
    const float* __restrict__ w2, const float* __restrict__ b2)
{
    extern __shared__ float sm[];
    float*    BsF[2] = { sm, sm + BS_FLOATS };
    uint32_t* Areg   = (uint32_t*)(sm + 2 * BS_FLOATS);       // h1 hi | h1 lo ; aliased by AsF
    uint32_t* Hh     = Areg;                                   // [128][HP]
    uint32_t* Hl     = Areg + 128 * HP;
    float*    AsF    = (float*)Areg;                           // [128][AS_STRIDE] fp32 (tf32 bits)
    float*    XsF    = sm + 2 * BS_FLOATS + AREG_W;
    float*    W1Th   = XsF + 2 * XS_FLOATS;
    float*    W1Tl   = W1Th + 8 * W1T_STRIDE;
    uint32_t* W2ph   = (uint32_t*)(W1Tl + 8 * W1T_STRIDE);     // [32][W2P_STRIDE]
    uint32_t* W2pl   = W2ph + 32 * W2P_STRIDE;
    float*    b1s    = (float*)(W2pl + 32 * W2P_STRIDE);
    float*    b2s    = b1s + 64;

    uint32_t sbase = smem_u32(sm);
    uint32_t bsA[2] = { sbase, sbase + BS_FLOATS * 4 };
    uint32_t xsA[2] = { sbase + (uint32_t)(2 * BS_FLOATS + AREG_W) * 4,
                        sbase + (uint32_t)(2 * BS_FLOATS + AREG_W + XS_FLOATS) * 4 };
    const uint32_t* XsU[2] = { (const uint32_t*)XsF,
                               (const uint32_t*)(XsF + XS_FLOATS) };

    int tid = threadIdx.x;
    int w = tid >> 5, lane = tid & 31, g = lane >> 2, tg = lane & 3;
    int row0 = blockIdx.x * 128;
    int sp = blockIdx.y;
    int q0  = (POS * sp) / SPLIT;
    int qe  = (POS * (sp + 1)) / SPLIT;
    int nch = qe - q0;

    // W1 tf32 hi/lo (transposed frag-friendly), biases
    for (int i = tid; i < 512; i += 256) {
        uint32_t hi, lo;
        split_tf32(__float_as_uint(w1[i]), hi, lo);
        W1Th[(i & 7) * W1T_STRIDE + (i >> 3)] = __uint_as_float(hi);
        W1Tl[(i & 7) * W1T_STRIDE + (i >> 3)] = __uint_as_float(lo);
    }
    // W2 bf16 hi/lo packed as k-pairs: W2p[kpair][o] = (bf16(w2[o][2kp]), bf16(w2[o][2kp+1]))
    for (int i = tid; i < 2048; i += 256) {
        int kp = i >> 6, o = i & 63;
        float v0 = w2[o * 64 + 2 * kp];
        float v1 = w2[o * 64 + 2 * kp + 1];
        __nv_bfloat16 h0 = __float2bfloat16_rn(v0);
        __nv_bfloat16 h1b = __float2bfloat16_rn(v1);
        float r0 = v0 - __bfloat162float(h0);
        float r1 = v1 - __bfloat162float(h1b);
        W2ph[kp * W2P_STRIDE + o] = pack_bf16x2(__bfloat162float(h0), __bfloat162float(h1b));
        W2pl[kp * W2P_STRIDE + o] = pack_bf16x2(r0, r1);
    }
    if (tid < 64) { b1s[tid] = b1[tid]; b2s[tid] = b2[tid]; }

    kf_load_chunk(bsA[0], xsA[0], q0, row0, tid);
    CP_COMMIT();

    float acc[4][8][4];
#pragma unroll
    for (int i = 0; i < 4; i++)
#pragma unroll
        for (int j = 0; j < 8; j++)
#pragma unroll
            for (int c = 0; c < 4; c++) acc[i][j][c] = 0.f;

    int wm = (w >> 2) * 64;
    int wn = (w & 3) * 64;
    int m1 = w * 16;

    const uint32_t* W1h = (const uint32_t*)W1Th;
    const uint32_t* W1l = (const uint32_t*)W1Tl;
    const uint32_t* AuC = (const uint32_t*)AsF;

    for (int it = 0; it < nch; it++) {
        int cur = it & 1;
        CP_WAIT0();
        __syncthreads();

        if (it + 1 < nch) {
            kf_load_chunk(bsA[cur ^ 1], xsA[cur ^ 1], q0 + it + 1, row0, tid);
            CP_COMMIT();
        }

        // ---- conv1 (tf32x3): C1[16x64] per warp; output -> packed bf16 h1 ----
        {
            const uint32_t* Xc = XsU[cur];
            uint32_t a[4], ah[4], al[4];
            a[0] = Xc[(m1 + g) * XS_STRIDE + tg];
            a[1] = Xc[(m1 + g + 8) * XS_STRIDE + tg];
            a[2] = Xc[(m1 + g) * XS_STRIDE + tg + 4];
            a[3] = Xc[(m1 + g + 8) * XS_STRIDE + tg + 4];
#pragma unroll
            for (int t = 0; t < 4; t++) split_tf32(a[t], ah[t], al[t]);
#pragma unroll
            for (int nt = 0; nt < 8; nt++) {
                uint32_t bh[2] = { W1h[tg * W1T_STRIDE + nt * 8 + g],
                                   W1h[(tg + 4) * W1T_STRIDE + nt * 8 + g] };
                uint32_t blo[2] = { W1l[tg * W1T_STRIDE + nt * 8 + g],
                                    W1l[(tg + 4) * W1T_STRIDE + nt * 8 + g] };
                float c[4] = { 0.f, 0.f, 0.f, 0.f };
                mma_tf32(c, ah, bh);
                mma_tf32(c, al, bh);
                mma_tf32(c, ah, blo);
                float bb0 = b1s[nt * 8 + 2 * tg], bb1 = b1s[nt * 8 + 2 * tg + 1];
                float v00 = fmaxf(c[0] + bb0, 0.f);
                float v01 = fmaxf(c[1] + bb1, 0.f);
                float v10 = fmaxf(c[2] + bb0, 0.f);
                float v11 = fmaxf(c[3] + bb1, 0.f);
                // split fp32 -> bf16 hi/lo, pack k-pairs
                __nv_bfloat16 h00 = __float2bfloat16_rn(v00);
                __nv_bfloat16 h01 = __float2bfloat16_rn(v01);
                __nv_bfloat16 h10 = __float2bfloat16_rn(v10);
                __nv_bfloat16 h11 = __float2bfloat16_rn(v11);
                int kp = nt * 4 + tg;
                Hh[(m1 + g) * HP + kp]     = pack_bf16x2(__bfloat162float(h00), __bfloat162float(h01));
                Hh[(m1 + g + 8) * HP + kp] = pack_bf16x2(__bfloat162float(h10), __bfloat162float(h11));
                Hl[(m1 + g) * HP + kp]     = pack_bf16x2(v00 - __bfloat162float(h00),
                                                         v01 - __bfloat162float(h01));
                Hl[(m1 + g + 8) * HP + kp] = pack_bf16x2(v10 - __bfloat162float(h10),
                                                         v11 - __bfloat162float(h11));
            }
        }
        __syncthreads();

        // ---- conv2 (bf16x3): S[16x64] per warp = h1[16x64] @ W2, 4 k16-steps ----
        float s[8][4];
#pragma unroll
        for (int nt = 0; nt < 8; nt++)
#pragma unroll
            for (int c = 0; c < 4; c++) s[nt][c] = 0.f;
#pragma unroll
        for (int ks = 0; ks < 4; ks++) {
            uint32_t ah[4], al[4];
            ah[0] = Hh[(m1 + g) * HP + ks * 8 + tg];
            ah[1] = Hh[(m1 + g + 8) * HP + ks * 8 + tg];
            ah[2] = Hh[(m1 + g) * HP + ks * 8 + tg + 4];
            ah[3] = Hh[(m1 + g + 8) * HP + ks * 8 + tg + 4];
            al[0] = Hl[(m1 + g) * HP + ks * 8 + tg];
            al[1] = Hl[(m1 + g + 8) * HP + ks * 8 + tg];
            al[2] = Hl[(m1 + g) * HP + ks * 8 + tg + 4];
            al[3] = Hl[(m1 + g + 8) * HP + ks * 8 + tg + 4];
#pragma unroll
            for (int nt = 0; nt < 8; nt++) {
                uint32_t bh[2] = { W2ph[(ks * 8 + tg) * W2P_STRIDE + nt * 8 + g],
                                   W2ph[(ks * 8 + tg + 4) * W2P_STRIDE + nt * 8 + g] };
                uint32_t blo[2] = { W2pl[(ks * 8 + tg) * W2P_STRIDE + nt * 8 + g],
                                    W2pl[(ks * 8 + tg + 4) * W2P_STRIDE + nt * 8 + g] };
                mma_bf16(s[nt], ah, bh);
                mma_bf16(s[nt], al, bh);
                mma_bf16(s[nt], ah, blo);
            }
        }
        __syncthreads();

        // ---- store S -> AsF (bias + relu + tf32 round; aliases h1 region) ----
#pragma unroll
        for (int nt = 0; nt < 8; nt++) {
            float bb0 = b2s[nt * 8 + 2 * tg], bb1 = b2s[nt * 8 + 2 * tg + 1];
            float2 p0, p1;
            p0.x = __uint_as_float(to_tf32(fmaxf(s[nt][0] + bb0, 0.f)));
            p0.y = __uint_as_float(to_tf32(fmaxf(s[nt][1] + bb1, 0.f)));
            p1.x = __uint_as_float(to_tf32(fmaxf(s[nt][2] + bb0, 0.f)));
            p1.y = __uint_as_float(to_tf32(fmaxf(s[nt][3] + bb1, 0.f)));
            *(float2*)&AsF[(m1 + g) * AS_STRIDE + nt * 8 + 2 * tg] = p0;
            *(float2*)&AsF[(m1 + g + 8) * AS_STRIDE + nt * 8 + 2 * tg] = p1;
        }
        __syncthreads();

        // ---- main: acc += A[128x64] @ Bq[64x256], 1-pass tf32 ----
        {
            const uint32_t* Bu = (const uint32_t*)BsF[cur];
#pragma unroll
            for (int ks = 0; ks < 8; ks++) {
                int k0 = ks * 8;
                uint32_t af[4][4];
#pragma unroll
                for (int im = 0; im < 4; im++) {
                    int rb = (wm + im * 16 + g) * AS_STRIDE + k0;
                    af[im][0] = AuC[rb + tg];
                    af[im][1] = AuC[rb + 8 * AS_STRIDE + tg];
                    af[im][2] = AuC[rb + tg + 4];
                    af[im][3] = AuC[rb + 8 * AS_STRIDE + tg + 4];
                }
                uint32_t bfr[8][2];
#pragma unroll
                for (int jn = 0; jn < 8; jn++) {
                    int cb = (k0 + tg) * BS_STRIDE + wn + jn * 8 + g;
                    bfr[jn][0] = Bu[cb];
                    bfr[jn][1] = Bu[cb + 4 * BS_STRIDE];
                }
#pragma unroll
                for (int im = 0; im < 4; im++)
#pragma unroll
                    for (int jn = 0; jn < 8; jn++)
                        mma_tf32(acc[im][jn], af[im], bfr[jn]);
            }
        }
    }

    float* Rp = g_Rpart + (size_t)sp * ROWS * JD;
#pragma unroll
    for (int im = 0; im < 4; im++) {
        int r = row0 + wm + im * 16 + g;
#pragma unroll
        for (int jn = 0; jn < 8; jn++) {
            int c = wn + jn * 8 + tg * 2;
            *(float2*)(Rp + (size_t)r * JD + c) =
                make_float2(acc[im][jn][0], acc[im][jn][1]);
            *(float2*)(Rp + (size_t)(r + 8) * JD + c) =
                make_float2(acc[im][jn][2], acc[im][jn][3]);
        }
    }
}

// ---------------- K3: split-K reduce + bias/relu + pl2 + Theta ----------------
__global__ void __launch_bounds__(256) k3_epi(
    const float* __restrict__ pl1_b,
    const float* __restrict__ pl2_b,
    float* __restrict__ outTheta)
{
    __shared__ float Hs[8][JD];
    __shared__ float Rls[8][J2D];
    int r0  = blockIdx.x * 8;
    int tid = threadIdx.x;

#pragma unroll
    for (int rr = 0; rr < 8; rr++) {
        size_t base = (size_t)(r0 + rr) * JD + tid;
        float s = 0.f;
#pragma unroll
        for (int sp = 0; sp < SPLIT; sp++)
            s += g_Rpart[(size_t)sp * ROWS * JD + base];
        Hs[rr][tid] = fmaxf(s + pl1_b[tid], 0.f);
    }
    __syncthreads();

    int j = tid & 127;
    int half = tid >> 7;
    float acc[4];
#pragma unroll
    for (int rr = 0; rr < 4; rr++) acc[rr] = pl2_b[j];
#pragma unroll 4
    for (int i = 0; i < JD; i++) {
        float w = g_pl2T[i * J2D + j];
#pragma unroll
        for (int rr = 0; rr < 4; rr++) acc[rr] += Hs[half * 4 + rr][i] * w;
    }
#pragma unroll
    for (int rr = 0; rr < 4; rr++) Rls[half * 4 + rr][j] = acc[rr];
    __syncthreads();

    for (int t = tid; t < 8 * N_; t += 256) {
        int rr = t >> 6, n = t & 63;
        float pr = Rls[rr][n];
        float pi = Rls[rr][n + N_];
        float nm = fmaxf(sqrtf(pr * pr + pi * pi), 1e-12f);
        float tr = pr / nm, ti = pi / nm;
        int r = r0 + rr;
        outTheta[((size_t)r * N_ + n) * 2 + 0] = tr;
        outTheta[((size_t)r * N_ + n) * 2 + 1] = ti;
        g_Theta[r * N_ + n] = tr;
        g_Theta[ROWS * N_ + r * N_ + n] = ti;
    }
}

// ---------------- K4: per-batch H einsums + MLP heads ----------------
__global__ void __launch_bounds__(256) k4_head(
    const float* __restrict__ H_re, const float* __restrict__ H_im,
    const float* __restrict__ ch_re, const float* __restrict__ ch_im,
    const float* __restrict__ b1_w, const float* __restrict__ b1_b,
    const float* __restrict__ b2_w, const float* __restrict__ b2_b,
    const float* __restrict__ b3_w, const float* __restrict__ b3_b,
    const float* __restrict__ p1_w, const float* __restrict__ p1_b,
    const float* __restrict__ p2_w, const float* __restrict__ p2_b,
    float* __restrict__ outW, float* __restrict__ outMu)
{
    int b = blockIdx.x;
    int tid = threadIdx.x;
    __shared__ float trs[256], tis[256];
    __shared__ float cHs[64], W1s[128], P1s[128], W2s[128], W3s[80];
    __shared__ float MUs[2], SCs[1];

    trs[tid] = g_Theta[b * 256 + tid];
    tis[tid] = g_Theta[ROWS * N_ + b * 256 + tid];
    __syncthreads();

    int out = tid >> 3;
    int g   = tid & 7;
    int kk  = out >> 3;
    int mm  = out & 7;
    const float* hre = H_re + (size_t)b * 8192;
    const float* him = H_im + (size_t)b * 8192;
    float s_rr = 0.f, s_ii = 0.f, s_ri = 0.f, s_ir = 0.f;
    for (int t = g; t < 256; t += 8) {
        int n = t >> 2, l = t & 3;
        float tr = trs[l * 64 + n];
        float ti = tis[l * 64 + n];
        int idx = mm * 1024 + n * 16 + l * 4 + kk;
        float hr = hre[idx];
        float hi = him[idx];
        s_rr += hr * tr; s_ii += hi * ti;
        s_ri += hr * ti; s_ir += hi * tr;
    }
#pragma unroll
    for (int off = 4; off; off >>= 1) {
        s_rr += __shfl_down_sync(0xffffffffu, s_rr, off, 8);
        s_ii += __shfl_down_sync(0xffffffffu, s_ii, off, 8);
        s_ri += __shfl_down_sync(0xffffffffu, s_ri, off, 8);
        s_ir += __shfl_down_sync(0xffffffffu, s_ir, off, 8);
    }
    if (g == 0) {
        cHs[kk * 16 + mm]     = s_rr + s_ii + ch_re[(b * 4 + kk) * 8 + mm];
        cHs[kk * 16 + 8 + mm] = s_ri - s_ir + ch_im[(b * 4 + kk) * 8 + mm];
    }
    __syncthreads();

    if (tid < 128) {
        float a = b1_b[tid];
        for (int c = 0; c < 64; c++) a += b1_w[tid * 64 + c] * cHs[c];
        W1s[tid] = fmaxf(a, 0.f);
    } else {
        int jj = tid - 128;
        float a = p1_b[jj];
        for (int c = 0; c < 64; c++) a += p1_w[jj * 64 + c] * cHs[c];
        P1s[jj] = fmaxf(a, 0.f);
    }
    __syncthreads();

    if (tid < 128) {
        float a = b2_b[tid];
        for (int c = 0; c < 128; c++) a += b2_w[tid * 128 + c] * W1s[c];
        W2s[tid] = fmaxf(a, 0.f);
    } else if (tid < 130) {
        int m2 = tid - 128;
        float a = p2_b[m2];
        for (int c = 0; c < 128; c++) a += p2_w[m2 * 128 + c] * P1s[c];
        MUs[m2] = a;
    }
    __syncthreads();

    if (tid < 80) {
        float a = b3_b[tid];
        for (int c = 0; c < 128; c++) a += b3_w[tid * 128 + c] * W2s[c];
        W3s[tid] = a;
    }
    __syncthreads();

    if (tid == 0) {
        float ss = 0.f;
        for (int j = 0; j < 80; j++) ss += W3s[j] * W3s[j];
        float wn = fmaxf(sqrtf(ss), 1e-12f);
        float mx = fmaxf(MUs[0], MUs[1]);
        float e0 = expf(MUs[0] - mx), e1 = expf(MUs[1] - mx);
        float mu0 = e0 / (e0 + e1);
        MUs[0] = mu0;
        MUs[1] = e1 / (e0 + e1);
        SCs[0] = sqrtf(10.0f) * sqrtf(mu0) / wn;
    }
    __syncthreads();

    if (tid < 80) outW[b * 80 + tid] = W3s[tid] * SCs[0];
    if (tid < 2)  outMu[b * 2 + tid] = MUs[tid];
}

// ---------------- launch ----------------
extern "C" void kernel_launch(void* const* d_in, const int* in_sizes, int n_in,
                              void* d_out, int out_size)
{
    const float* x       = (const float*)d_in[0];
    const float* H_re    = (const float*)d_in[1];
    const float* H_im    = (const float*)d_in[2];
    const float* ch_re   = (const float*)d_in[3];
    const float* ch_im   = (const float*)d_in[4];
    const float* conv1_w = (const float*)d_in[5];
    const float* conv1_b = (const float*)d_in[6];
    const float* conv2_w = (const float*)d_in[7];
    const float* conv2_b = (const float*)d_in[8];
    const float* pl1_w   = (const float*)d_in[9];
    const float* pl1_b   = (const float*)d_in[10];
    const float* pl2_w   = (const float*)d_in[11];
    const float* pl2_b   = (const float*)d_in[12];
    const float* b1_w    = (const float*)d_in[13];
    const float* b1_b    = (const float*)d_in[14];
    const float* b2_w    = (const float*)d_in[15];
    const float* b2_b    = (const float*)d_in[16];
    const float* b3_w    = (const float*)d_in[17];
    const float* b3_b    = (const float*)d_in[18];
    const float* p1_w    = (const float*)d_in[19];
    const float* p1_b    = (const float*)d_in[20];
    const float* p2_w    = (const float*)d_in[21];
    const float* p2_b    = (const float*)d_in[22];

    float* out      = (float*)d_out;
    float* outW     = out;
    float* outTheta = out + OFF_THETA;
    float* outMu    = out + OFF_MU;

    cudaFuncSetAttribute(kF, cudaFuncAttributeMaxDynamicSharedMemorySize, KF_DYN);

    k0_transpose<<<128, 256>>>(pl2_w);
    k0x<<<(ROWS * POS) / 256, 256>>>(x);
    dim3 gp(FLAT / 32, JD / 32);
    k0p<<<gp, 256>>>(pl1_w);
    dim3 gf(ROWS / 128, SPLIT);
    kF<<<gf, 256, KF_DYN>>>(conv1_w, conv1_b, conv2_w, conv2_b);
    k3_epi<<<ROWS / 8, 256>>>(pl1_b, pl2_b, outTheta);
    k4_head<<<B_, 256>>>(H_re, H_im, ch_re, ch_im,
                         b1_w, b1_b, b2_w, b2_b, b3_w, b3_b,
                         p1_w, p1_b, p2_w, p2_b, outW, outMu);
}

// round 8
// speedup vs baseline: 3.3535x; 1.1962x over previous
#include <cuda_runtime.h>
#include <cuda_bf16.h>
#include <math.h>
#include <stdint.h>

// ---------------- problem constants ----------------
#define B_    512
#define L_    4
#define M_    8
#define N_    64
#define NP1   65
#define POS   520           // M_*NP1
#define FLAT  33280         // 64*POS
#define ROWS  2048          // B_*L_
#define JD    256           // pl1 out
#define J2D   128           // pl2 out

#define SPLIT 9             // q-splits (144 CTAs on 148 SMs)

// output layout: W (512*80) | Theta (2048*64*2) | mu (512*2)
#define OFF_THETA 40960
#define OFF_MU    (40960 + 262144)

// ---------------- scratch ----------------
__device__ float g_Bw[(size_t)FLAT * JD];             // permuted pl1_w: [q][o][j] (tf32)
__device__ float g_xT[(size_t)ROWS * POS * 8];        // x transposed: [bl][q][c] (fp32)
__device__ float g_Rpart[(size_t)SPLIT * ROWS * JD];  // split-K partials
__device__ float g_Theta[2 * ROWS * N_];              // tr | ti
__device__ float g_pl2T[JD * J2D];                    // pl2_w transposed

// ---------------- helpers ----------------
__device__ __forceinline__ uint32_t to_tf32(float v) {
    uint32_t u;
    asm("cvt.rna.tf32.f32 %0, %1;" : "=r"(u) : "f"(v));
    return u;
}
__device__ __forceinline__ void split_tf32(uint32_t v, uint32_t& hi, uint32_t& lo) {
    float f = __uint_as_float(v);
    uint32_t h = to_tf32(f);
    float fl = f - __uint_as_float(h);
    hi = h;
    lo = to_tf32(fl);
}
__device__ __forceinline__ uint32_t pack_bf16x2(float a, float b) {
    __nv_bfloat162 h = __floats2bfloat162_rn(a, b);
    return *(uint32_t*)&h;
}
__device__ __forceinline__ uint32_t smem_u32(const void* p) {
    uint32_t a;
    asm("{ .reg .u64 t; cvta.to.shared.u64 t, %1; cvt.u32.u64 %0, t; }" : "=r"(a) : "l"(p));
    return a;
}
#define CPASYNC16(sa, gp)  asm volatile("cp.async.cg.shared.global [%0], [%1], 16;" :: "r"(sa), "l"(gp) : "memory")
#define CP_COMMIT()        asm volatile("cp.async.commit_group;" ::: "memory")
#define CP_WAIT0()         asm volatile("cp.async.wait_group 0;" ::: "memory")

__device__ __forceinline__ void mma_tf32(float* d, const uint32_t* a, const uint32_t* b) {
    asm volatile(
        "mma.sync.aligned.m16n8k8.row.col.f32.tf32.tf32.f32 "
        "{%0,%1,%2,%3}, {%4,%5,%6,%7}, {%8,%9}, {%0,%1,%2,%3};"
        : "+f"(d[0]), "+f"(d[1]), "+f"(d[2]), "+f"(d[3])
        : "r"(a[0]), "r"(a[1]), "r"(a[2]), "r"(a[3]), "r"(b[0]), "r"(b[1]));
}
__device__ __forceinline__ void mma_bf16(float* d, const uint32_t* a, const uint32_t* b) {
    asm volatile(
        "mma.sync.aligned.m16n8k16.row.col.f32.bf16.bf16.f32 "
        "{%0,%1,%2,%3}, {%4,%5,%6,%7}, {%8,%9}, {%0,%1,%2,%3};"
        : "+f"(d[0]), "+f"(d[1]), "+f"(d[2]), "+f"(d[3])
        : "r"(a[0]), "r"(a[1]), "r"(a[2]), "r"(a[3]), "r"(b[0]), "r"(b[1]));
}

// ---------------- K0: transpose pl2_w (128x256 -> 256x128) ----------------
__global__ void k0_transpose(const float* __restrict__ pl2_w) {
    int idx = blockIdx.x * 256 + threadIdx.x;
    int i = idx >> 7;
    int j = idx & 127;
    g_pl2T[idx] = pl2_w[j * JD + i];
}

// ---------------- K0x: x -> xq[bl][q][c], raw fp32 ----------------
__global__ void __launch_bounds__(256) k0x(const float* __restrict__ x) {
    int tl = blockIdx.x * 256 + threadIdx.x;
    int bl = tl / POS;
    int q  = tl - bl * POS;
    const float* xp = x + (size_t)bl * (8 * POS) + q;
    float4 v0, v1;
    v0.x = xp[0 * POS]; v0.y = xp[1 * POS]; v0.z = xp[2 * POS]; v0.w = xp[3 * POS];
    v1.x = xp[4 * POS]; v1.y = xp[5 * POS]; v1.z = xp[6 * POS]; v1.w = xp[7 * POS];
    float4* dst = (float4*)(g_xT + (size_t)tl * 8);
    dst[0] = v0;
    dst[1] = v1;
}

// ---------------- K0p: permute pl1_w [j][k] -> Bp[q][o][j], tf32 ----------
__global__ void __launch_bounds__(256) k0p(const float* __restrict__ pl1_w) {
    __shared__ float ts[32][33];
    int k0 = blockIdx.x * 32;
    int j0 = blockIdx.y * 32;
    int tx = threadIdx.x & 31;
    int ty = threadIdx.x >> 5;
#pragma unroll
    for (int r = 0; r < 4; r++) {
        int j = j0 + ty + r * 8;
        ts[ty + r * 8][tx] = pl1_w[(size_t)j * FLAT + k0 + tx];
    }
    __syncthreads();
#pragma unroll
    for (int r = 0; r < 4; r++) {
        int k = k0 + ty + r * 8;
        int o = k / POS;
        int q = k - o * POS;
        g_Bw[((size_t)q * 64 + o) * JD + j0 + tx] =
            __uint_as_float(to_tf32(ts[tx][ty + r * 8]));
    }
}

// ---------------- KF: fused conv1+conv2+pl1 GEMM ----------------
// conv1 tf32x3 -> registers (D-frag == conv2 A-frag), conv2 bf16x3 in regs,
// S -> smem (tf32), main GEMM tf32 1-pass. 2 syncthreads per chunk.
#define BS_STRIDE 264
#define BS_FLOATS (64 * BS_STRIDE)       // 16896
#define AS_STRIDE 68
#define AS_FLOATS (128 * AS_STRIDE)      // 8704
#define XS_STRIDE 12
#define XS_FLOATS (128 * XS_STRIDE)      // 1536
#define W1T_STRIDE 72
#define W2P_STRIDE 72
#define KF_WORDS (2*BS_FLOATS + AS_FLOATS + 2*XS_FLOATS + 2*8*W1T_STRIDE + 2*32*W2P_STRIDE + 128)
#define KF_DYN   (KF_WORDS * 4)          // 205,824 B

__device__ __forceinline__ void kf_load_chunk(
    uint32_t bsA, uint32_t xsA, int q, int row0, int tid)
{
    const float* Bq = g_Bw + (size_t)q * (64 * JD);
#pragma unroll
    for (int k = 0; k < 16; k++) {
        int u = tid + k * 256;
        int o = u >> 6, jq = u & 63;
        CPASYNC16(bsA + (uint32_t)(o * BS_STRIDE + jq * 4) * 4, Bq + (size_t)u * 4);
    }
    {
        int r = tid >> 1, half = tid & 1;
        const float* src = g_xT + ((size_t)(row0 + r) * POS + q) * 8 + half * 4;
        CPASYNC16(xsA + (uint32_t)(r * XS_STRIDE + half * 4) * 4, src);
    }
}

__global__ void __launch_bounds__(256, 1) kF(
    const float* __restrict__ w1, const float* __restrict__ b1,
    const float* __restrict__ w2, const float* __restrict__ b2)
{
    extern __shared__ float sm[];
    float*    BsF[2] = { sm, sm + BS_FLOATS };
    float*    AsF    = sm + 2 * BS_FLOATS;                     // [128][AS_STRIDE]
    float*    XsF    = AsF + AS_FLOATS;
    float*    W1Th   = XsF + 2 * XS_FLOATS;
    float*    W1Tl   = W1Th + 8 * W1T_STRIDE;
    uint32_t* W2ph   = (uint32_t*)(W1Tl + 8 * W1T_STRIDE);     // [32][W2P_STRIDE]
    uint32_t* W2pl   = W2ph + 32 * W2P_STRIDE;
    float*    b1s    = (float*)(W2pl + 32 * W2P_STRIDE);
    float*    b2s    = b1s + 64;

    uint32_t sbase = smem_u32(sm);
    uint32_t bsA[2] = { sbase, sbase + BS_FLOATS * 4 };
    uint32_t xsA[2] = { sbase + (uint32_t)(2 * BS_FLOATS + AS_FLOATS) * 4,
                        sbase + (uint32_t)(2 * BS_FLOATS + AS_FLOATS + XS_FLOATS) * 4 };
    const uint32_t* XsU[2] = { (const uint32_t*)XsF,
                               (const uint32_t*)(XsF + XS_FLOATS) };

    int tid = threadIdx.x;
    int w = tid >> 5, lane = tid & 31, g = lane >> 2, tg = lane & 3;
    int row0 = blockIdx.x * 128;
    int sp = blockIdx.y;
    int q0  = (POS * sp) / SPLIT;
    int qe  = (POS * (sp + 1)) / SPLIT;
    int nch = qe - q0;

    for (int i = tid; i < 512; i += 256) {
        uint32_t hi, lo;
        split_tf32(__float_as_uint(w1[i]), hi, lo);
        W1Th[(i & 7) * W1T_STRIDE + (i >> 3)] = __uint_as_float(hi);
        W1Tl[(i & 7) * W1T_STRIDE + (i >> 3)] = __uint_as_float(lo);
    }
    for (int i = tid; i < 2048; i += 256) {
        int kp = i >> 6, o = i & 63;
        float v0 = w2[o * 64 + 2 * kp];
        float v1 = w2[o * 64 + 2 * kp + 1];
        __nv_bfloat16 h0 = __float2bfloat16_rn(v0);
        __nv_bfloat16 h1b = __float2bfloat16_rn(v1);
        float r0 = v0 - __bfloat162float(h0);
        float r1 = v1 - __bfloat162float(h1b);
        W2ph[kp * W2P_STRIDE + o] = pack_bf16x2(__bfloat162float(h0), __bfloat162float(h1b));
        W2pl[kp * W2P_STRIDE + o] = pack_bf16x2(r0, r1);
    }
    if (tid < 64) { b1s[tid] = b1[tid]; b2s[tid] = b2[tid]; }

    kf_load_chunk(bsA[0], xsA[0], q0, row0, tid);
    CP_COMMIT();

    float acc[4][8][4];
#pragma unroll
    for (int i = 0; i < 4; i++)
#pragma unroll
        for (int j = 0; j < 8; j++)
#pragma unroll
            for (int c = 0; c < 4; c++) acc[i][j][c] = 0.f;

    int wm = (w >> 2) * 64;
    int wn = (w & 3) * 64;
    int m1 = w * 16;

    const uint32_t* W1h = (const uint32_t*)W1Th;
    const uint32_t* W1l = (const uint32_t*)W1Tl;
    const uint32_t* AuC = (const uint32_t*)AsF;

    for (int it = 0; it < nch; it++) {
        int cur = it & 1;
        CP_WAIT0();
        __syncthreads();   // Bs/Xs[cur] ready; also fences previous main's AsF reads

        if (it + 1 < nch) {
            kf_load_chunk(bsA[cur ^ 1], xsA[cur ^ 1], q0 + it + 1, row0, tid);
            CP_COMMIT();
        }

        // ---- conv1 (tf32x3) + conv2 (bf16x3), fully register-resident ----
        float s[8][4];
#pragma unroll
        for (int nt = 0; nt < 8; nt++)
#pragma unroll
            for (int c = 0; c < 4; c++) s[nt][c] = 0.f;
        {
            const uint32_t* Xc = XsU[cur];
            uint32_t a[4], xh[4], xl[4];
            a[0] = Xc[(m1 + g) * XS_STRIDE + tg];
            a[1] = Xc[(m1 + g + 8) * XS_STRIDE + tg];
            a[2] = Xc[(m1 + g) * XS_STRIDE + tg + 4];
            a[3] = Xc[(m1 + g + 8) * XS_STRIDE + tg + 4];
#pragma unroll
            for (int t = 0; t < 4; t++) split_tf32(a[t], xh[t], xl[t]);

#pragma unroll
            for (int ks = 0; ks < 4; ks++) {
                uint32_t pah[4], pal[4];   // conv2 A-frags (hi/lo) for this k16 step
#pragma unroll
                for (int h = 0; h < 2; h++) {
                    int nt = 2 * ks + h;
                    uint32_t bh[2] = { W1h[tg * W1T_STRIDE + nt * 8 + g],
                                       W1h[(tg + 4) * W1T_STRIDE + nt * 8 + g] };
                    uint32_t blo[2] = { W1l[tg * W1T_STRIDE + nt * 8 + g],
                                        W1l[(tg + 4) * W1T_STRIDE + nt * 8 + g] };
                    float c[4] = { 0.f, 0.f, 0.f, 0.f };
                    mma_tf32(c, xh, bh);
                    mma_tf32(c, xl, bh);
                    mma_tf32(c, xh, blo);
                    float bb0 = b1s[nt * 8 + 2 * tg], bb1 = b1s[nt * 8 + 2 * tg + 1];
                    float v00 = fmaxf(c[0] + bb0, 0.f);
                    float v01 = fmaxf(c[1] + bb1, 0.f);
                    float v10 = fmaxf(c[2] + bb0, 0.f);
                    float v11 = fmaxf(c[3] + bb1, 0.f);
                    __nv_bfloat16 h00 = __float2bfloat16_rn(v00);
                    __nv_bfloat16 h01 = __float2bfloat16_rn(v01);
                    __nv_bfloat16 h10 = __float2bfloat16_rn(v10);
                    __nv_bfloat16 h11 = __float2bfloat16_rn(v11);
                    pah[2 * h]     = pack_bf16x2(__bfloat162float(h00), __bfloat162float(h01));
                    pah[2 * h + 1] = pack_bf16x2(__bfloat162float(h10), __bfloat162float(h11));
                    pal[2 * h]     = pack_bf16x2(v00 - __bfloat162float(h00),
                                                 v01 - __bfloat162float(h01));
                    pal[2 * h + 1] = pack_bf16x2(v10 - __bfloat162float(h10),
                                                 v11 - __bfloat162float(h11));
                }
                // rearrange: A-frag order is {rowg lo8, rowg+8 lo8, rowg hi8, rowg+8 hi8}
                uint32_t ah[4] = { pah[0], pah[1], pah[2], pah[3] };
                uint32_t al[4] = { pal[0], pal[1], pal[2], pal[3] };
#pragma unroll
                for (int nt = 0; nt < 8; nt++) {
                    uint32_t bh[2] = { W2ph[(ks * 8 + tg) * W2P_STRIDE + nt * 8 + g],
                                       W2ph[(ks * 8 + tg + 4) * W2P_STRIDE + nt * 8 + g] };
                    uint32_t blo[2] = { W2pl[(ks * 8 + tg) * W2P_STRIDE + nt * 8 + g],
                                        W2pl[(ks * 8 + tg + 4) * W2P_STRIDE + nt * 8 + g] };
                    mma_bf16(s[nt], ah, bh);
                    mma_bf16(s[nt], al, bh);
                    mma_bf16(s[nt], ah, blo);
                }
            }
        }

        // ---- store S -> AsF (bias + relu + tf32 round) ----
#pragma unroll
        for (int nt = 0; nt < 8; nt++) {
            float bb0 = b2s[nt * 8 + 2 * tg], bb1 = b2s[nt * 8 + 2 * tg + 1];
            float2 p0, p1;
            p0.x = __uint_as_float(to_tf32(fmaxf(s[nt][0] + bb0, 0.f)));
            p0.y = __uint_as_float(to_tf32(fmaxf(s[nt][1] + bb1, 0.f)));
            p1.x = __uint_as_float(to_tf32(fmaxf(s[nt][2] + bb0, 0.f)));
            p1.y = __uint_as_float(to_tf32(fmaxf(s[nt][3] + bb1, 0.f)));
            *(float2*)&AsF[(m1 + g) * AS_STRIDE + nt * 8 + 2 * tg] = p0;
            *(float2*)&AsF[(m1 + g + 8) * AS_STRIDE + nt * 8 + 2 * tg] = p1;
        }
        __syncthreads();

        // ---- main: acc += A[128x64] @ Bq[64x256], 1-pass tf32 ----
        {
            const uint32_t* Bu = (const uint32_t*)BsF[cur];
#pragma unroll
            for (int ks = 0; ks < 8; ks++) {
                int k0 = ks * 8;
                uint32_t af[4][4];
#pragma unroll
                for (int im = 0; im < 4; im++) {
                    int rb = (wm + im * 16 + g) * AS_STRIDE + k0;
                    af[im][0] = AuC[rb + tg];
                    af[im][1] = AuC[rb + 8 * AS_STRIDE + tg];
                    af[im][2] = AuC[rb + tg + 4];
                    af[im][3] = AuC[rb + 8 * AS_STRIDE + tg + 4];
                }
                uint32_t bfr[8][2];
#pragma unroll
                for (int jn = 0; jn < 8; jn++) {
                    int cb = (k0 + tg) * BS_STRIDE + wn + jn * 8 + g;
                    bfr[jn][0] = Bu[cb];
                    bfr[jn][1] = Bu[cb + 4 * BS_STRIDE];
                }
#pragma unroll
                for (int im = 0; im < 4; im++)
#pragma unroll
                    for (int jn = 0; jn < 8; jn++)
                        mma_tf32(acc[im][jn], af[im], bfr[jn]);
            }
        }
    }

    float* Rp = g_Rpart + (size_t)sp * ROWS * JD;
#pragma unroll
    for (int im = 0; im < 4; im++) {
        int r = row0 + wm + im * 16 + g;
#pragma unroll
        for (int jn = 0; jn < 8; jn++) {
            int c = wn + jn * 8 + tg * 2;
            *(float2*)(Rp + (size_t)r * JD + c) =
                make_float2(acc[im][jn][0], acc[im][jn][1]);
            *(float2*)(Rp + (size_t)(r + 8) * JD + c) =
                make_float2(acc[im][jn][2], acc[im][jn][3]);
        }
    }
}

// ---------------- K3: split-K reduce + bias/relu + pl2 + Theta ----------------
__global__ void __launch_bounds__(256) k3_epi(
    const float* __restrict__ pl1_b,
    const float* __restrict__ pl2_b,
    float* __restrict__ outTheta)
{
    __shared__ float Hs[8][JD];
    __shared__ float Rls[8][J2D];
    int r0  = blockIdx.x * 8;
    int tid = threadIdx.x;

#pragma unroll
    for (int rr = 0; rr < 8; rr++) {
        size_t base = (size_t)(r0 + rr) * JD + tid;
        float s = 0.f;
#pragma unroll
        for (int sp = 0; sp < SPLIT; sp++)
            s += g_Rpart[(size_t)sp * ROWS * JD + base];
        Hs[rr][tid] = fmaxf(s + pl1_b[tid], 0.f);
    }
    __syncthreads();

    int j = tid & 127;
    int half = tid >> 7;
    float acc[4];
#pragma unroll
    for (int rr = 0; rr < 4; rr++) acc[rr] = pl2_b[j];
#pragma unroll 4
    for (int i = 0; i < JD; i++) {
        float w = g_pl2T[i * J2D + j];
#pragma unroll
        for (int rr = 0; rr < 4; rr++) acc[rr] += Hs[half * 4 + rr][i] * w;
    }
#pragma unroll
    for (int rr = 0; rr < 4; rr++) Rls[half * 4 + rr][j] = acc[rr];
    __syncthreads();

    for (int t = tid; t < 8 * N_; t += 256) {
        int rr = t >> 6, n = t & 63;
        float pr = Rls[rr][n];
        float pi = Rls[rr][n + N_];
        float nm = fmaxf(sqrtf(pr * pr + pi * pi), 1e-12f);
        float tr = pr / nm, ti = pi / nm;
        int r = r0 + rr;
        outTheta[((size_t)r * N_ + n) * 2 + 0] = tr;
        outTheta[((size_t)r * N_ + n) * 2 + 1] = ti;
        g_Theta[r * N_ + n] = tr;
        g_Theta[ROWS * N_ + r * N_ + n] = ti;
    }
}

// ---------------- K4: per-batch H einsums + MLP heads ----------------
__global__ void __launch_bounds__(256) k4_head(
    const float* __restrict__ H_re, const float* __restrict__ H_im,
    const float* __restrict__ ch_re, const float* __restrict__ ch_im,
    const float* __restrict__ b1_w, const float* __restrict__ b1_b,
    const float* __restrict__ b2_w, const float* __restrict__ b2_b,
    const float* __restrict__ b3_w, const float* __restrict__ b3_b,
    const float* __restrict__ p1_w, const float* __restrict__ p1_b,
    const float* __restrict__ p2_w, const float* __restrict__ p2_b,
    float* __restrict__ outW, float* __restrict__ outMu)
{
    int b = blockIdx.x;
    int tid = threadIdx.x;
    __shared__ float trs[256], tis[256];
    __shared__ float cHs[64], W1s[128], P1s[128], W2s[128], W3s[80];
    __shared__ float MUs[2], SCs[1];

    trs[tid] = g_Theta[b * 256 + tid];
    tis[tid] = g_Theta[ROWS * N_ + b * 256 + tid];
    __syncthreads();

    // coalesced einsum: warp w handles m=w; lane = (dn<<4)|(l<<2)|kk
    {
        int w = tid >> 5, lane = tid & 31;
        int kk = lane & 3, l = (lane >> 2) & 3, dn = lane >> 4;
        const float* hre = H_re + (size_t)b * 8192 + w * 1024;
        const float* him = H_im + (size_t)b * 8192 + w * 1024;
        float s_rr = 0.f, s_ii = 0.f, s_ri = 0.f, s_ir = 0.f;
#pragma unroll 4
        for (int ng = 0; ng < 32; ng++) {
            int n = ng * 2 + dn;
            float tr = trs[l * 64 + n];
            float ti = tis[l * 64 + n];
            float hr = hre[ng * 32 + lane];
            float hi = him[ng * 32 + lane];
            s_rr += hr * tr; s_ii += hi * ti;
            s_ri += hr * ti; s_ir += hi * tr;
        }
#pragma unroll
        for (int off = 4; off < 32; off <<= 1) {
            s_rr += __shfl_xor_sync(0xffffffffu, s_rr, off);
            s_ii += __shfl_xor_sync(0xffffffffu, s_ii, off);
            s_ri += __shfl_xor_sync(0xffffffffu, s_ri, off);
            s_ir += __shfl_xor_sync(0xffffffffu, s_ir, off);
        }
        if (lane < 4) {
            cHs[kk * 16 + w]     = s_rr + s_ii + ch_re[(b * 4 + kk) * 8 + w];
            cHs[kk * 16 + 8 + w] = s_ri - s_ir + ch_im[(b * 4 + kk) * 8 + w];
        }
    }
    __syncthreads();

    if (tid < 128) {
        float a = b1_b[tid];
        for (int c = 0; c < 64; c++) a += b1_w[tid * 64 + c] * cHs[c];
        W1s[tid] = fmaxf(a, 0.f);
    } else {
        int jj = tid - 128;
        float a = p1_b[jj];
        for (int c = 0; c < 64; c++) a += p1_w[jj * 64 + c] * cHs[c];
        P1s[jj] = fmaxf(a, 0.f);
    }
    __syncthreads();

    if (tid < 128) {
        float a = b2_b[tid];
        for (int c = 0; c < 128; c++) a += b2_w[tid * 128 + c] * W1s[c];
        W2s[tid] = fmaxf(a, 0.f);
    } else if (tid < 130) {
        int m2 = tid - 128;
        float a = p2_b[m2];
        for (int c = 0; c < 128; c++) a += p2_w[m2 * 128 + c] * P1s[c];
        MUs[m2] = a;
    }
    __syncthreads();

    if (tid < 80) {
        float a = b3_b[tid];
        for (int c = 0; c < 128; c++) a += b3_w[tid * 128 + c] * W2s[c];
        W3s[tid] = a;
    }
    __syncthreads();

    if (tid == 0) {
        float ss = 0.f;
        for (int j = 0; j < 80; j++) ss += W3s[j] * W3s[j];
        float wn = fmaxf(sqrtf(ss), 1e-12f);
        float mx = fmaxf(MUs[0], MUs[1]);
        float e0 = expf(MUs[0] - mx), e1 = expf(MUs[1] - mx);
        float mu0 = e0 / (e0 + e1);
        MUs[0] = mu0;
        MUs[1] = e1 / (e0 + e1);
        SCs[0] = sqrtf(10.0f) * sqrtf(mu0) / wn;
    }
    __syncthreads();

    if (tid < 80) outW[b * 80 + tid] = W3s[tid] * SCs[0];
    if (tid < 2)  outMu[b * 2 + tid] = MUs[tid];
}

// ---------------- launch ----------------
extern "C" void kernel_launch(void* const* d_in, const int* in_sizes, int n_in,
                              void* d_out, int out_size)
{
    const float* x       = (const float*)d_in[0];
    const float* H_re    = (const float*)d_in[1];
    const float* H_im    = (const float*)d_in[2];
    const float* ch_re   = (const float*)d_in[3];
    const float* ch_im   = (const float*)d_in[4];
    const float* conv1_w = (const float*)d_in[5];
    const float* conv1_b = (const float*)d_in[6];
    const float* conv2_w = (const float*)d_in[7];
    const float* conv2_b = (const float*)d_in[8];
    const float* pl1_w   = (const float*)d_in[9];
    const float* pl1_b   = (const float*)d_in[10];
    const float* pl2_w   = (const float*)d_in[11];
    const float* pl2_b   = (const float*)d_in[12];
    const float* b1_w    = (const float*)d_in[13];
    const float* b1_b    = (const float*)d_in[14];
    const float* b2_w    = (const float*)d_in[15];
    const float* b2_b    = (const float*)d_in[16];
    const float* b3_w    = (const float*)d_in[17];
    const float* b3_b    = (const float*)d_in[18];
    const float* p1_w    = (const float*)d_in[19];
    const float* p1_b    = (const float*)d_in[20];
    const float* p2_w    = (const float*)d_in[21];
    const float* p2_b    = (const float*)d_in[22];

    float* out      = (float*)d_out;
    float* outW     = out;
    float* outTheta = out + OFF_THETA;
    float* outMu    = out + OFF_MU;

    cudaFuncSetAttribute(kF, cudaFuncAttributeMaxDynamicSharedMemorySize, KF_DYN);

    k0_transpose<<<128, 256>>>(pl2_w);
    k0x<<<(ROWS * POS) / 256, 256>>>(x);
    dim3 gp(FLAT / 32, JD / 32);
    k0p<<<gp, 256>>>(pl1_w);
    dim3 gf(ROWS / 128, SPLIT);
    kF<<<gf, 256, KF_DYN>>>(conv1_w, conv1_b, conv2_w, conv2_b);
    k3_epi<<<ROWS / 8, 256>>>(pl1_b, pl2_b, outTheta);
    k4_head<<<B_, 256>>>(H_re, H_im, ch_re, ch_im,
                         b1_w, b1_b, b2_w, b2_b, b3_w, b3_b,
                         p1_w, p1_b, p2_w, p2_b, outW, outMu);
}